// round 14
// baseline (speedup 1.0000x reference)
#include <cuda_runtime.h>
#include <cuda_bf16.h>
#include <cstdint>

#define NSs   5000
#define NMm   100000
#define NRr   2000
#define HH    128
#define ESM   2000000
#define ERM   1000000
#define ESIM  2000000
#define LL    500000
#define KTM   640      // m GEMM K: 5 slices x 128
#define KT2   256      // s/r GEMM K
#define NCM   10       // m chunks of 64

#define CDIV(a,b) (((a)+(b)-1)/(b))

// ---------------- device scratch ----------------
static __device__ float g_XS[2][NSs*HH];
static __device__ float g_XM[2][NMm*HH];
static __device__ float g_XR[2][NRr*HH];

static __device__ __nv_bfloat16 g_Ash[(size_t)NSs*KT2];
static __device__ __nv_bfloat16 g_Asl[(size_t)NSs*KT2];
static __device__ __nv_bfloat16 g_Arh[(size_t)NRr*KT2];
static __device__ __nv_bfloat16 g_Arl[(size_t)NRr*KT2];

static __device__ __nv_bfloat16 g_Bmh[HH*KTM], g_Bml[HH*KTM];
static __device__ __nv_bfloat16 g_Bsh[HH*KT2], g_Bsl[HH*KT2];
static __device__ __nv_bfloat16 g_Brh[HH*KT2], g_Brl[HH*KT2];
static __device__ float g_biasM[HH];

static __device__ int g_adj0[ESM];
static __device__ int g_adj1[ESM];
static __device__ int g_adj2[ERM];
static __device__ int g_adj3[ERM];
static __device__ int g_adj4[ESIM];
static __device__ int g_adj5[ESIM];

static __device__ int g_off0[NMm+1];
static __device__ int g_off1[NSs+1];
static __device__ int g_off2[NMm+1];
static __device__ int g_off3[NRr+1];
static __device__ int g_off4[NMm+1];
static __device__ int g_off5[NMm+1];

#define CNT_O0 0
#define CNT_O1 (NMm)
#define CNT_O2 (NMm+NSs)
#define CNT_O3 (2*NMm+NSs)
#define CNT_O4 (2*NMm+NSs+NRr)
#define CNT_O5 (3*NMm+NSs+NRr)
#define CNT_TOT (4*NMm+NSs+NRr)
static __device__ int g_cnt6[CNT_TOT];
static __device__ int g_incl6[CNT_TOT];
static __device__ int g_cur6[CNT_TOT];
static __device__ int g_bsums6[6*1024];

static __device__ float g_dinvF[NMm];
static __device__ float g_dinvR[NMm];

// ---------------- bf16 hi/lo split helper ----------------
__device__ __forceinline__ void split_store4(float a, float b, float c, float d,
                                             __nv_bfloat16* oh, __nv_bfloat16* ol){
    __nv_bfloat16 ha = __float2bfloat16(a), hb = __float2bfloat16(b),
                  hc = __float2bfloat16(c), hd = __float2bfloat16(d);
    __nv_bfloat16 la = __float2bfloat16(a - __bfloat162float(ha));
    __nv_bfloat16 lb = __float2bfloat16(b - __bfloat162float(hb));
    __nv_bfloat16 lc = __float2bfloat16(c - __bfloat162float(hc));
    __nv_bfloat16 ld = __float2bfloat16(d - __bfloat162float(hd));
    ushort4 H; H.x = __bfloat16_as_ushort(ha); H.y = __bfloat16_as_ushort(hb);
               H.z = __bfloat16_as_ushort(hc); H.w = __bfloat16_as_ushort(hd);
    ushort4 L; L.x = __bfloat16_as_ushort(la); L.y = __bfloat16_as_ushort(lb);
               L.z = __bfloat16_as_ushort(lc); L.w = __bfloat16_as_ushort(ld);
    *(ushort4*)oh = H;
    *(ushort4*)ol = L;
}

// ================= batched CSR build (R11-proven) =================
#define NB_E2M CDIV(ESM,256)
#define NB_E1M CDIV(ERM,256)
#define EDGE_BLKS (4*NB_E2M + 2*NB_E1M)
#define SB_NM CDIV(NMm,1024)
#define SB_NS CDIV(NSs,1024)
#define SB_NR CDIV(NRr,1024)
#define SCAN_BLKS (4*SB_NM + SB_NS + SB_NR)

struct CsrArgs {
    const int *k0,*k1,*k2,*k3,*k4,*k5;
    const int *v0,*v1,*v2,*v3,*v4,*v5;
};
struct OffPtrs  { int *o0,*o1,*o2,*o3,*o4,*o5; };
struct AdjPtrs  { int *a0,*a1,*a2,*a3,*a4,*a5; };

__device__ __forceinline__ void seg6_edges(int b, int& seg, int& lb){
    if      (b < NB_E2M)                      { seg=0; lb=b; }
    else if (b < 2*NB_E2M)                    { seg=1; lb=b-NB_E2M; }
    else if (b < 2*NB_E2M+NB_E1M)             { seg=2; lb=b-2*NB_E2M; }
    else if (b < 2*NB_E2M+2*NB_E1M)           { seg=3; lb=b-2*NB_E2M-NB_E1M; }
    else if (b < 3*NB_E2M+2*NB_E1M)           { seg=4; lb=b-2*NB_E2M-2*NB_E1M; }
    else                                      { seg=5; lb=b-3*NB_E2M-2*NB_E1M; }
}
__device__ __forceinline__ void seg6_scan(int b, int& seg, int& lb){
    if      (b < SB_NM)                      { seg=0; lb=b; }
    else if (b < SB_NM+SB_NS)                { seg=1; lb=b-SB_NM; }
    else if (b < 2*SB_NM+SB_NS)              { seg=2; lb=b-SB_NM-SB_NS; }
    else if (b < 2*SB_NM+SB_NS+SB_NR)        { seg=3; lb=b-2*SB_NM-SB_NS; }
    else if (b < 3*SB_NM+SB_NS+SB_NR)        { seg=4; lb=b-2*SB_NM-SB_NS-SB_NR; }
    else                                     { seg=5; lb=b-3*SB_NM-SB_NS-SB_NR; }
}
__device__ __forceinline__ void seg_scan_params(int seg, int& n, int& co){
    switch(seg){
        case 0: n=NMm; co=CNT_O0; break;
        case 1: n=NSs; co=CNT_O1; break;
        case 2: n=NMm; co=CNT_O2; break;
        case 3: n=NRr; co=CNT_O3; break;
        case 4: n=NMm; co=CNT_O4; break;
        default:n=NMm; co=CNT_O5; break;
    }
}

__global__ void k_zero_i(int* p, int n){
    int i = blockIdx.x*blockDim.x + threadIdx.x;
    if (i < n) p[i] = 0;
}
__global__ void k_count_all(CsrArgs a, int* __restrict__ cnt){
    int seg, lb; seg6_edges(blockIdx.x, seg, lb);
    int i = lb*256 + threadIdx.x;
    const int* key; int e, co;
    switch(seg){
        case 0: key=a.k0; e=ESM;  co=CNT_O0; break;
        case 1: key=a.k1; e=ESM;  co=CNT_O1; break;
        case 2: key=a.k2; e=ERM;  co=CNT_O2; break;
        case 3: key=a.k3; e=ERM;  co=CNT_O3; break;
        case 4: key=a.k4; e=ESIM; co=CNT_O4; break;
        default:key=a.k5; e=ESIM; co=CNT_O5; break;
    }
    if (i < e) atomicAdd(&cnt[co + key[i]], 1);
}
__global__ void k_scan1_all(const int* __restrict__ cnt, int* __restrict__ incl,
                            int* __restrict__ bsums){
    __shared__ int sh[1024];
    int seg, lb; seg6_scan(blockIdx.x, seg, lb);
    int n, co; seg_scan_params(seg, n, co);
    int i = lb*1024 + threadIdx.x;
    sh[threadIdx.x] = (i < n) ? cnt[co + i] : 0;
    __syncthreads();
    for (int d = 1; d < 1024; d <<= 1){
        int t = (threadIdx.x >= d) ? sh[threadIdx.x - d] : 0;
        __syncthreads();
        sh[threadIdx.x] += t;
        __syncthreads();
    }
    if (i < n) incl[co + i] = sh[threadIdx.x];
    if (threadIdx.x == 1023) bsums[seg*1024 + lb] = sh[1023];
}
__global__ void k_scan2_all(int* bsums){
    __shared__ int sh[1024];
    int seg = blockIdx.x;
    int n, co; seg_scan_params(seg, n, co);
    int nb = CDIV(n, 1024);
    sh[threadIdx.x] = (threadIdx.x < nb) ? bsums[seg*1024 + threadIdx.x] : 0;
    __syncthreads();
    for (int d = 1; d < 1024; d <<= 1){
        int t = (threadIdx.x >= d) ? sh[threadIdx.x - d] : 0;
        __syncthreads();
        sh[threadIdx.x] += t;
        __syncthreads();
    }
    if (threadIdx.x < nb) bsums[seg*1024 + threadIdx.x] = sh[threadIdx.x];
}
__global__ void k_scan3_all(const int* __restrict__ incl, const int* __restrict__ bsums,
                            const int* __restrict__ cnt, OffPtrs op, int* __restrict__ cur){
    int seg, lb; seg6_scan(blockIdx.x, seg, lb);
    int n, co; seg_scan_params(seg, n, co);
    int* off;
    switch(seg){ case 0: off=op.o0; break; case 1: off=op.o1; break; case 2: off=op.o2; break;
                 case 3: off=op.o3; break; case 4: off=op.o4; break; default: off=op.o5; break; }
    int i = lb*1024 + threadIdx.x;
    if (i < n){
        int add = lb ? bsums[seg*1024 + lb - 1] : 0;
        int v = incl[co + i] + add;
        off[i+1] = v;
        if (i == 0) off[0] = 0;
        cur[co + i] = v - cnt[co + i];
    }
}
__global__ void k_fill_all(CsrArgs a, AdjPtrs ap, int* __restrict__ cur){
    int seg, lb; seg6_edges(blockIdx.x, seg, lb);
    int i = lb*256 + threadIdx.x;
    const int *key, *val; int e, co; int* adj;
    switch(seg){
        case 0: key=a.k0; val=a.v0; e=ESM;  co=CNT_O0; adj=ap.a0; break;
        case 1: key=a.k1; val=a.v1; e=ESM;  co=CNT_O1; adj=ap.a1; break;
        case 2: key=a.k2; val=a.v2; e=ERM;  co=CNT_O2; adj=ap.a2; break;
        case 3: key=a.k3; val=a.v3; e=ERM;  co=CNT_O3; adj=ap.a3; break;
        case 4: key=a.k4; val=a.v4; e=ESIM; co=CNT_O4; adj=ap.a4; break;
        default:key=a.k5; val=a.v5; e=ESIM; co=CNT_O5; adj=ap.a5; break;
    }
    if (i < e){
        int p = atomicAdd(&cur[co + key[i]], 1);
        adj[p] = val[i];
    }
}
__global__ void k_dinv2(const int* __restrict__ off4, const int* __restrict__ off5,
                        float* __restrict__ dF, float* __restrict__ dR){
    int i = blockIdx.x*blockDim.x + threadIdx.x;
    if (i < NMm){
        dF[i] = rsqrtf((float)(off4[i+1] - off4[i] + 1));
        dR[i] = rsqrtf((float)(off5[i+1] - off5[i] + 1));
    }
}

// ---------------- weight-stack / bias builders ----------------
// m-B layout: [Wl0 | Wl2 | gW0 | gW1 | Wsum]  (matches fused slice order, root last)
__global__ void k_buildB_m(const float* __restrict__ Wl0, const float* __restrict__ Wl2,
                           const float* __restrict__ Wr0, const float* __restrict__ Wr2,
                           const float* __restrict__ gW0, const float* __restrict__ gW1,
                           __nv_bfloat16* __restrict__ oh, __nv_bfloat16* __restrict__ ol){
    int i = blockIdx.x*blockDim.x + threadIdx.x;
    if (i >= HH*KTM) return;
    int n = i / KTM, k = i % KTM;
    int sl = k >> 7, kk = k & 127;
    float v;
    if      (sl == 0) v = Wl0[kk*HH + n];
    else if (sl == 1) v = Wl2[kk*HH + n];
    else if (sl == 2) v = gW0[kk*HH + n];
    else if (sl == 3) v = gW1[kk*HH + n];
    else              v = Wr0[kk*HH + n] + Wr2[kk*HH + n];
    __nv_bfloat16 h = __float2bfloat16(v);
    oh[i] = h;
    ol[i] = __float2bfloat16(v - __bfloat162float(h));
}
__global__ void k_buildB_2(const float* __restrict__ Wa, const float* __restrict__ Wb,
                           __nv_bfloat16* __restrict__ oh, __nv_bfloat16* __restrict__ ol){
    int i = blockIdx.x*blockDim.x + threadIdx.x;
    if (i >= HH*KT2) return;
    int n = i / KT2, k = i % KT2;
    float v = (k < 128) ? Wa[(k&127)*HH + n] : Wb[(k&127)*HH + n];
    __nv_bfloat16 h = __float2bfloat16(v);
    oh[i] = h;
    ol[i] = __float2bfloat16(v - __bfloat162float(h));
}
__global__ void k_bias4(const float* a, const float* b, const float* c, const float* d, float* o){
    int i = threadIdx.x;
    if (i < HH) o[i] = a[i] + b[i] + c[i] + d[i];
}

// ---------------- s/r aggregation + root staging (R12-proven) ----------------
__global__ void k_agg_mean(const float* __restrict__ X, const int* __restrict__ adj,
                           const int* __restrict__ off, int n,
                           __nv_bfloat16* __restrict__ oh, __nv_bfloat16* __restrict__ ol,
                           int Kt, int coloff){
    int w = (blockIdx.x*blockDim.x + threadIdx.x) >> 5;
    int lane = threadIdx.x & 31;
    if (w >= n) return;
    int beg = off[w], end = off[w+1];
    int c = lane * 4;
    float4 acc = make_float4(0.f, 0.f, 0.f, 0.f);
    int j = beg;
    for (; j + 4 <= end; j += 4){
        int n0 = adj[j], n1 = adj[j+1], n2 = adj[j+2], n3 = adj[j+3];
        float4 v0 = *(const float4*)(X + (size_t)n0*HH + c);
        float4 v1 = *(const float4*)(X + (size_t)n1*HH + c);
        float4 v2 = *(const float4*)(X + (size_t)n2*HH + c);
        float4 v3 = *(const float4*)(X + (size_t)n3*HH + c);
        acc.x += v0.x + v1.x + v2.x + v3.x;
        acc.y += v0.y + v1.y + v2.y + v3.y;
        acc.z += v0.z + v1.z + v2.z + v3.z;
        acc.w += v0.w + v1.w + v2.w + v3.w;
    }
    for (; j < end; j++){
        int nb = adj[j];
        float4 v = *(const float4*)(X + (size_t)nb*HH + c);
        acc.x += v.x; acc.y += v.y; acc.z += v.z; acc.w += v.w;
    }
    int cnt = end - beg;
    float inv = 1.f / (float)(cnt > 1 ? cnt : 1);
    size_t base = (size_t)w*Kt + coloff + c;
    split_store4(acc.x*inv, acc.y*inv, acc.z*inv, acc.w*inv, oh + base, ol + base);
}

__global__ void k_root(const float* __restrict__ X,
                       __nv_bfloat16* __restrict__ oh, __nv_bfloat16* __restrict__ ol,
                       int n, int Kt, int coloff){
    int idx = blockIdx.x*blockDim.x + threadIdx.x;
    if (idx >= n*32) return;
    int w = idx >> 5, c4 = (idx & 31) * 4;
    float4 v = *(const float4*)(X + (size_t)w*HH + c4);
    size_t base = (size_t)w*Kt + coloff + c4;
    split_store4(v.x, v.y, v.z, v.w, oh + base, ol + base);
}

// ---------------- shared GEMM machinery ----------------
#define LDSB 72
#define SM_BUF (128*LDSB)
#define SM_BUF_BYTES (SM_BUF*2)            // 18432

__device__ __forceinline__ uint32_t smem_u32(const void* p){
    uint32_t a;
    asm("{ .reg .u64 t; cvta.to.shared.u64 t, %1; cvt.u32.u64 %0, t; }" : "=r"(a) : "l"(p));
    return a;
}
#define CP_ASYNC16(dst, src, sz) \
    asm volatile("cp.async.cg.shared.global [%0], [%1], 16, %2;" :: "r"(dst), "l"(src), "r"(sz))
#define CP_COMMIT() asm volatile("cp.async.commit_group;" ::: "memory")
#define CP_WAIT1()  asm volatile("cp.async.wait_group 1;" ::: "memory")
#define CP_WAIT0()  asm volatile("cp.async.wait_group 0;" ::: "memory")

__device__ __forceinline__ void mma_bf16(float* c, const uint32_t* a, const uint32_t* b){
    asm volatile(
        "mma.sync.aligned.m16n8k16.row.col.f32.bf16.bf16.f32 "
        "{%0,%1,%2,%3}, {%4,%5,%6,%7}, {%8,%9}, {%0,%1,%2,%3};"
        : "+f"(c[0]), "+f"(c[1]), "+f"(c[2]), "+f"(c[3])
        : "r"(a[0]), "r"(a[1]), "r"(a[2]), "r"(a[3]), "r"(b[0]), "r"(b[1]));
}

// one 64-K MMA chunk from smem tiles (shared by both GEMM kernels)
__device__ __forceinline__ void mma_chunk(float acc[4][4][4],
    const __nv_bfloat16* sAh, const __nv_bfloat16* sAl,
    const __nv_bfloat16* sBh, const __nv_bfloat16* sBl,
    int warp_m, int warp_n, int g, int t2)
{
    #pragma unroll
    for (int ks = 0; ks < 4; ks++){
        const int k0 = ks * 16;
        uint32_t afh[4][4], afl[4][4], bfh[4][2], bfl[4][2];
        #pragma unroll
        for (int mt = 0; mt < 4; mt++){
            int rbase = warp_m*64 + mt*16;
            #pragma unroll
            for (int r = 0; r < 4; r++){
                int row = rbase + g + (r & 1)*8;
                int col = k0 + t2*2 + (r >> 1)*8;
                afh[mt][r] = *(const uint32_t*)(sAh + row*LDSB + col);
                afl[mt][r] = *(const uint32_t*)(sAl + row*LDSB + col);
            }
        }
        #pragma unroll
        for (int nt = 0; nt < 4; nt++){
            int nrow = warp_n*32 + nt*8 + g;
            #pragma unroll
            for (int r = 0; r < 2; r++){
                int col = k0 + t2*2 + r*8;
                bfh[nt][r] = *(const uint32_t*)(sBh + nrow*LDSB + col);
                bfl[nt][r] = *(const uint32_t*)(sBl + nrow*LDSB + col);
            }
        }
        #pragma unroll
        for (int mt = 0; mt < 4; mt++)
            #pragma unroll
            for (int nt = 0; nt < 4; nt++){
                mma_bf16(acc[mt][nt], afh[mt], bfh[nt]);
                mma_bf16(acc[mt][nt], afh[mt], bfl[nt]);
                mma_bf16(acc[mt][nt], afl[mt], bfh[nt]);
            }
    }
}

__device__ __forceinline__ void epilogue(float acc[4][4][4], const float* bias,
    float* Xout, int n, int row0, int warp_m, int warp_n, int g, int t2)
{
    #pragma unroll
    for (int mt = 0; mt < 4; mt++){
        #pragma unroll
        for (int nt = 0; nt < 4; nt++){
            int col = warp_n*32 + nt*8 + t2*2;
            float b0 = bias[col], b1 = bias[col+1];
            int r0 = row0 + warp_m*64 + mt*16 + g;
            if (r0 < n){
                float2 o;
                o.x = fmaxf(acc[mt][nt][0] + b0, 0.f);
                o.y = fmaxf(acc[mt][nt][1] + b1, 0.f);
                *(float2*)(Xout + (size_t)r0*HH + col) = o;
            }
            int r1 = r0 + 8;
            if (r1 < n){
                float2 o;
                o.x = fmaxf(acc[mt][nt][2] + b0, 0.f);
                o.y = fmaxf(acc[mt][nt][3] + b1, 0.f);
                *(float2*)(Xout + (size_t)r1*HH + col) = o;
            }
        }
    }
}

// ---------------- s/r GEMM: R12-exact cp.async pipeline ----------------
#define STAGE_BYTES (4*SM_BUF_BYTES)
#define SMEM_MMA2_BYTES (2*STAGE_BYTES)    // 147456

__global__ void __launch_bounds__(256)
k_mma2(const __nv_bfloat16* __restrict__ Ah, const __nv_bfloat16* __restrict__ Al,
       const __nv_bfloat16* __restrict__ Bh, const __nv_bfloat16* __restrict__ Bl,
       const float* __restrict__ bias, float* __restrict__ Xout, int n, int Ktot)
{
    extern __shared__ char smem[];
    const uint32_t sbase = smem_u32(smem);
    const int tid  = threadIdx.x;
    const int wid  = tid >> 5;
    const int lane = tid & 31;
    const int g    = lane >> 2;
    const int t2   = lane & 3;
    const int warp_m = wid & 1;
    const int warp_n = wid >> 1;
    const int row0 = blockIdx.x * 128;
    const int NC = Ktot >> 6;

    float acc[4][4][4];
    #pragma unroll
    for (int mt = 0; mt < 4; mt++)
        #pragma unroll
        for (int nt = 0; nt < 4; nt++)
            #pragma unroll
            for (int r = 0; r < 4; r++) acc[mt][nt][r] = 0.f;

    auto issue = [&](int cch){
        const int stg = cch & 1;
        const uint32_t stb = sbase + stg*STAGE_BYTES;
        const int kc = cch << 6;
        #pragma unroll
        for (int j = 0; j < 4; j++){
            int idx = tid + j*256;
            int row = idx >> 3, c8 = idx & 7;
            uint32_t soff = (uint32_t)(row*LDSB + c8*8) * 2;
            int gr = row0 + row;
            uint32_t sza = (gr < n) ? 16u : 0u;
            CP_ASYNC16(stb + 0*SM_BUF_BYTES + soff, (const char*)(Ah + (size_t)gr*Ktot + kc + c8*8), sza);
            CP_ASYNC16(stb + 1*SM_BUF_BYTES + soff, (const char*)(Al + (size_t)gr*Ktot + kc + c8*8), sza);
            CP_ASYNC16(stb + 2*SM_BUF_BYTES + soff, (const char*)(Bh + (size_t)row*Ktot + kc + c8*8), 16u);
            CP_ASYNC16(stb + 3*SM_BUF_BYTES + soff, (const char*)(Bl + (size_t)row*Ktot + kc + c8*8), 16u);
        }
    };

    issue(0); CP_COMMIT();
    if (NC > 1){ issue(1); CP_COMMIT(); }

    for (int cch = 0; cch < NC; cch++){
        if (cch + 1 < NC) CP_WAIT1(); else CP_WAIT0();
        __syncthreads();
        const int stg = cch & 1;
        const __nv_bfloat16* sAh = (const __nv_bfloat16*)(smem + stg*STAGE_BYTES);
        mma_chunk(acc, sAh, sAh + SM_BUF, sAh + 2*SM_BUF, sAh + 3*SM_BUF, warp_m, warp_n, g, t2);
        __syncthreads();
        if (cch + 2 < NC){ issue(cch + 2); CP_COMMIT(); }
    }

    epilogue(acc, bias, Xout, n, row0, warp_m, warp_n, g, t2);
}

// ---------------- fused m-target: gather->convert->MMA per slice ----------------
// smem: F fp32 [128x128]=65536 | A tiles (h0,l0,h1,l1)=73728 | B stages 2x(h,l)=73728
#define FUS_F_OFF 0
#define FUS_A_OFF 65536
#define FUS_B_OFF (65536+73728)
#define SMEM_FUSED_BYTES (65536+73728+73728)   // 212992

__global__ void __launch_bounds__(256)
k_fusedM(const float* __restrict__ xs, const int* __restrict__ adj0, const int* __restrict__ off0,
         const float* __restrict__ xr, const int* __restrict__ adj2, const int* __restrict__ off2,
         const float* __restrict__ xm, const int* __restrict__ adj4, const int* __restrict__ off4,
         const float* __restrict__ dinvF,
         const int* __restrict__ adj5, const int* __restrict__ off5, const float* __restrict__ dinvR,
         const __nv_bfloat16* __restrict__ Bh, const __nv_bfloat16* __restrict__ Bl,
         const float* __restrict__ bias, float* __restrict__ Xout, int n)
{
    extern __shared__ char smem[];
    const uint32_t sbase = smem_u32(smem);
    float* F = (float*)(smem + FUS_F_OFF);
    const int tid  = threadIdx.x;
    const int wid  = tid >> 5;
    const int lane = tid & 31;
    const int g    = lane >> 2;
    const int t2   = lane & 3;
    const int warp_m = wid & 1;
    const int warp_n = wid >> 1;
    const int row0 = blockIdx.x * 128;

    float acc[4][4][4];
    #pragma unroll
    for (int mt = 0; mt < 4; mt++)
        #pragma unroll
        for (int nt = 0; nt < 4; nt++)
            #pragma unroll
            for (int r = 0; r < 4; r++) acc[mt][nt][r] = 0.f;

    auto issueB = [&](int cc){
        const uint32_t bb = sbase + FUS_B_OFF + (cc & 1)*(2*SM_BUF_BYTES);
        const int kc = cc << 6;
        #pragma unroll
        for (int j = 0; j < 4; j++){
            int idx = tid + j*256;
            int row = idx >> 3, c8 = idx & 7;
            uint32_t soff = (uint32_t)(row*LDSB + c8*8) * 2;
            CP_ASYNC16(bb + soff,                (const char*)(Bh + (size_t)row*KTM + kc + c8*8), 16u);
            CP_ASYNC16(bb + SM_BUF_BYTES + soff, (const char*)(Bl + (size_t)row*KTM + kc + c8*8), 16u);
        }
    };

    issueB(0); CP_COMMIT();
    issueB(1); CP_COMMIT();

    for (int sl = 0; sl < 5; sl++){
        // ---- gather slice sl into F (fp32) ----
        const int c = lane * 4;
        for (int rr = wid; rr < 128; rr += 8){
            int node = row0 + rr;
            float4 out = make_float4(0.f, 0.f, 0.f, 0.f);
            if (node < n){
                if (sl == 4){
                    out = *(const float4*)(xm + (size_t)node*HH + c);
                } else if (sl < 2){
                    const float* X = (sl == 0) ? xs : xr;
                    const int* adj = (sl == 0) ? adj0 : adj2;
                    const int* off = (sl == 0) ? off0 : off2;
                    int beg = off[node], end = off[node+1];
                    float4 a4 = make_float4(0.f,0.f,0.f,0.f);
                    int j = beg;
                    for (; j + 4 <= end; j += 4){
                        int n0 = adj[j], n1 = adj[j+1], n2 = adj[j+2], n3 = adj[j+3];
                        float4 v0 = *(const float4*)(X + (size_t)n0*HH + c);
                        float4 v1 = *(const float4*)(X + (size_t)n1*HH + c);
                        float4 v2 = *(const float4*)(X + (size_t)n2*HH + c);
                        float4 v3 = *(const float4*)(X + (size_t)n3*HH + c);
                        a4.x += v0.x + v1.x + v2.x + v3.x;
                        a4.y += v0.y + v1.y + v2.y + v3.y;
                        a4.z += v0.z + v1.z + v2.z + v3.z;
                        a4.w += v0.w + v1.w + v2.w + v3.w;
                    }
                    for (; j < end; j++){
                        float4 v = *(const float4*)(X + (size_t)adj[j]*HH + c);
                        a4.x += v.x; a4.y += v.y; a4.z += v.z; a4.w += v.w;
                    }
                    int cnt = end - beg;
                    float inv = 1.f / (float)(cnt > 1 ? cnt : 1);
                    out = make_float4(a4.x*inv, a4.y*inv, a4.z*inv, a4.w*inv);
                } else {
                    const int* adj = (sl == 2) ? adj4 : adj5;
                    const int* off = (sl == 2) ? off4 : off5;
                    const float* dv = (sl == 2) ? dinvF : dinvR;
                    int beg = off[node], end = off[node+1];
                    float wd = dv[node];
                    float4 xx = *(const float4*)(xm + (size_t)node*HH + c);
                    float ws = wd * wd;
                    float4 a4 = make_float4(ws*xx.x, ws*xx.y, ws*xx.z, ws*xx.w);
                    int j = beg;
                    for (; j + 4 <= end; j += 4){
                        int n0 = adj[j], n1 = adj[j+1], n2 = adj[j+2], n3 = adj[j+3];
                        float w0 = wd*dv[n0], w1 = wd*dv[n1], w2 = wd*dv[n2], w3 = wd*dv[n3];
                        float4 v0 = *(const float4*)(xm + (size_t)n0*HH + c);
                        float4 v1 = *(const float4*)(xm + (size_t)n1*HH + c);
                        float4 v2 = *(const float4*)(xm + (size_t)n2*HH + c);
                        float4 v3 = *(const float4*)(xm + (size_t)n3*HH + c);
                        a4.x += w0*v0.x + w1*v1.x + w2*v2.x + w3*v3.x;
                        a4.y += w0*v0.y + w1*v1.y + w2*v2.y + w3*v3.y;
                        a4.z += w0*v0.z + w1*v1.z + w2*v2.z + w3*v3.z;
                        a4.w += w0*v0.w + w1*v1.w + w2*v2.w + w3*v3.w;
                    }
                    for (; j < end; j++){
                        int nb = adj[j];
                        float wn = wd * dv[nb];
                        float4 v = *(const float4*)(xm + (size_t)nb*HH + c);
                        a4.x += wn*v.x; a4.y += wn*v.y; a4.z += wn*v.z; a4.w += wn*v.w;
                    }
                    out = a4;
                }
            }
            *(float4*)(F + rr*128 + c) = out;
        }
        __syncthreads();

        // ---- convert F -> A tiles (hi/lo, two 64-col chunks) ----
        #pragma unroll
        for (int j = 0; j < 16; j++){
            int u = tid + j*256;                 // float4 unit id, 4096 total
            int row = u >> 5, c4 = (u & 31) * 4;
            int h = c4 >> 6, cl = c4 & 63;
            float4 v = *(const float4*)(F + row*128 + c4);
            __nv_bfloat16* Ah = (__nv_bfloat16*)(smem + FUS_A_OFF + h*(2*SM_BUF_BYTES));
            __nv_bfloat16* Al = Ah + SM_BUF;
            split_store4(v.x, v.y, v.z, v.w, Ah + row*LDSB + cl, Al + row*LDSB + cl);
        }
        // (h0 chunk's barrier below orders these writes before MMA)

        #pragma unroll
        for (int h = 0; h < 2; h++){
            int cc = sl*2 + h;
            if (cc + 1 < NCM) CP_WAIT1(); else CP_WAIT0();
            __syncthreads();
            const __nv_bfloat16* sAh = (const __nv_bfloat16*)(smem + FUS_A_OFF + h*(2*SM_BUF_BYTES));
            const __nv_bfloat16* sBh = (const __nv_bfloat16*)(smem + FUS_B_OFF + (cc & 1)*(2*SM_BUF_BYTES));
            mma_chunk(acc, sAh, sAh + SM_BUF, sBh, sBh + SM_BUF, warp_m, warp_n, g, t2);
            __syncthreads();
            if (cc + 2 < NCM){ issueB(cc + 2); CP_COMMIT(); }
        }
    }

    epilogue(acc, bias, Xout, n, row0, warp_m, warp_n, g, t2);
}

// ---------------- fused readout ----------------
__global__ void k_pred(const float* __restrict__ XS, const float* __restrict__ XM,
                       const float* __restrict__ XR,
                       const int* __restrict__ ls, const int* __restrict__ lm,
                       const int* __restrict__ lr, float* __restrict__ out){
    int w = (blockIdx.x*blockDim.x + threadIdx.x) >> 5;
    int lane = threadIdx.x & 31;
    if (w >= LL) return;
    const float* m = XM + (size_t)lm[w]*HH;
    const float* s = XS + (size_t)ls[w]*HH;
    const float* r = XR + (size_t)lr[w]*HH;
    float4 vm = *(const float4*)(m + lane*4);
    float4 vs = *(const float4*)(s + lane*4);
    float4 vr = *(const float4*)(r + lane*4);
    float ds = vs.x*vm.x + vs.y*vm.y + vs.z*vm.z + vs.w*vm.w;
    float dr = vr.x*vm.x + vr.y*vm.y + vr.z*vm.z + vr.w*vm.w;
    #pragma unroll
    for (int d = 16; d; d >>= 1){
        ds += __shfl_xor_sync(0xffffffffu, ds, d);
        dr += __shfl_xor_sync(0xffffffffu, dr, d);
    }
    if (lane == 0){ out[w] = ds; out[LL + w] = dr; }
}

// ---------------- host ----------------
static inline void* symaddr(const void* sym){
    void* p = nullptr;
    cudaGetSymbolAddress(&p, sym);
    return p;
}

extern "C" void kernel_launch(void* const* d_in, const int* in_sizes, int n_in,
                              void* d_out, int out_size){
    const float* emb_s  = (const float*)d_in[0];
    const float* emb_m  = (const float*)d_in[1];
    const float* emb_r  = (const float*)d_in[2];
    const float* sageWl = (const float*)d_in[3];
    const float* sageBl = (const float*)d_in[4];
    const float* sageWr = (const float*)d_in[5];
    const float* gcnW   = (const float*)d_in[6];
    const float* gcnB   = (const float*)d_in[7];
    const int* src_sm   = (const int*)d_in[8];
    const int* dst_sm   = (const int*)d_in[9];
    const int* src_rm   = (const int*)d_in[10];
    const int* dst_rm   = (const int*)d_in[11];
    const int* src_sim  = (const int*)d_in[12];
    const int* dst_sim  = (const int*)d_in[13];
    const int* lbl_s    = (const int*)d_in[14];
    const int* lbl_m    = (const int*)d_in[15];
    const int* lbl_r    = (const int*)d_in[16];
    float* out = (float*)d_out;

    cudaFuncSetAttribute(k_mma2,  cudaFuncAttributeMaxDynamicSharedMemorySize, SMEM_MMA2_BYTES);
    cudaFuncSetAttribute(k_fusedM, cudaFuncAttributeMaxDynamicSharedMemorySize, SMEM_FUSED_BYTES);

    float* XS = (float*)symaddr(g_XS);
    float* XM = (float*)symaddr(g_XM);
    float* XR = (float*)symaddr(g_XR);
    __nv_bfloat16* Ash = (__nv_bfloat16*)symaddr(g_Ash);
    __nv_bfloat16* Asl = (__nv_bfloat16*)symaddr(g_Asl);
    __nv_bfloat16* Arh = (__nv_bfloat16*)symaddr(g_Arh);
    __nv_bfloat16* Arl = (__nv_bfloat16*)symaddr(g_Arl);
    __nv_bfloat16* Bmh = (__nv_bfloat16*)symaddr(g_Bmh);
    __nv_bfloat16* Bml = (__nv_bfloat16*)symaddr(g_Bml);
    __nv_bfloat16* Bsh = (__nv_bfloat16*)symaddr(g_Bsh);
    __nv_bfloat16* Bsl = (__nv_bfloat16*)symaddr(g_Bsl);
    __nv_bfloat16* Brh = (__nv_bfloat16*)symaddr(g_Brh);
    __nv_bfloat16* Brl = (__nv_bfloat16*)symaddr(g_Brl);
    float* biasM = (float*)symaddr(g_biasM);
    int* adj0 = (int*)symaddr(g_adj0);
    int* adj1 = (int*)symaddr(g_adj1);
    int* adj2 = (int*)symaddr(g_adj2);
    int* adj3 = (int*)symaddr(g_adj3);
    int* adj4 = (int*)symaddr(g_adj4);
    int* adj5 = (int*)symaddr(g_adj5);
    int* off0 = (int*)symaddr(g_off0);
    int* off1 = (int*)symaddr(g_off1);
    int* off2 = (int*)symaddr(g_off2);
    int* off3 = (int*)symaddr(g_off3);
    int* off4 = (int*)symaddr(g_off4);
    int* off5 = (int*)symaddr(g_off5);
    int* cnt6  = (int*)symaddr(g_cnt6);
    int* incl6 = (int*)symaddr(g_incl6);
    int* cur6  = (int*)symaddr(g_cur6);
    int* bsum6 = (int*)symaddr(g_bsums6);
    float* dinvF = (float*)symaddr(g_dinvF);
    float* dinvR = (float*)symaddr(g_dinvR);

    // ---- batched CSR build ----
    CsrArgs ca;
    ca.k0 = dst_sm;  ca.v0 = src_sm;
    ca.k1 = src_sm;  ca.v1 = dst_sm;
    ca.k2 = dst_rm;  ca.v2 = src_rm;
    ca.k3 = src_rm;  ca.v3 = dst_rm;
    ca.k4 = dst_sim; ca.v4 = src_sim;
    ca.k5 = src_sim; ca.v5 = dst_sim;
    OffPtrs op = { off0, off1, off2, off3, off4, off5 };
    AdjPtrs ap = { adj0, adj1, adj2, adj3, adj4, adj5 };

    k_zero_i<<<CDIV(CNT_TOT,256),256>>>(cnt6, CNT_TOT);
    k_count_all<<<EDGE_BLKS,256>>>(ca, cnt6);
    k_scan1_all<<<SCAN_BLKS,1024>>>(cnt6, incl6, bsum6);
    k_scan2_all<<<6,1024>>>(bsum6);
    k_scan3_all<<<SCAN_BLKS,1024>>>(incl6, bsum6, cnt6, op, cur6);
    k_fill_all<<<EDGE_BLKS,256>>>(ca, ap, cur6);
    k_dinv2<<<CDIV(NMm,256),256>>>(off4, off5, dinvF, dinvR);

    const int HW = HH*HH;

    for (int l = 0; l < 2; l++){
        const float* xs = l ? XS : emb_s;
        const float* xm = l ? XM : emb_m;
        const float* xr = l ? XR : emb_r;
        float* XSo = XS + (size_t)l*NSs*HH;
        float* XMo = XM + (size_t)l*NMm*HH;
        float* XRo = XR + (size_t)l*NRr*HH;

        const float* Wl0 = sageWl + (size_t)(l*4+0)*HW;
        const float* Wl1 = sageWl + (size_t)(l*4+1)*HW;
        const float* Wl2 = sageWl + (size_t)(l*4+2)*HW;
        const float* Wl3 = sageWl + (size_t)(l*4+3)*HW;
        const float* bl0 = sageBl + (size_t)(l*4+0)*HH;
        const float* bl1 = sageBl + (size_t)(l*4+1)*HH;
        const float* bl2 = sageBl + (size_t)(l*4+2)*HH;
        const float* bl3 = sageBl + (size_t)(l*4+3)*HH;
        const float* Wr0 = sageWr + (size_t)(l*4+0)*HW;
        const float* Wr1 = sageWr + (size_t)(l*4+1)*HW;
        const float* Wr2 = sageWr + (size_t)(l*4+2)*HW;
        const float* Wr3 = sageWr + (size_t)(l*4+3)*HW;
        const float* gW0 = gcnW + (size_t)(l*2+0)*HW;
        const float* gW1 = gcnW + (size_t)(l*2+1)*HW;
        const float* gb0 = gcnB + (size_t)(l*2+0)*HH;
        const float* gb1 = gcnB + (size_t)(l*2+1)*HH;

        // weight stacks + fused bias
        k_buildB_m<<<CDIV(HH*KTM,256),256>>>(Wl0, Wl2, Wr0, Wr2, gW0, gW1, Bmh, Bml);
        k_buildB_2<<<CDIV(HH*KT2,256),256>>>(Wl1, Wr1, Bsh, Bsl);
        k_buildB_2<<<CDIV(HH*KT2,256),256>>>(Wl3, Wr3, Brh, Brl);
        k_bias4<<<1,128>>>(bl0, bl2, gb0, gb1, biasM);

        // s/r staged A: [mean from m | root]
        k_agg_mean<<<CDIV(NSs,8),256>>>(xm, adj1, off1, NSs, Ash, Asl, KT2, 0);
        k_root<<<CDIV(NSs*32,256),256>>>(xs, Ash, Asl, NSs, KT2, 128);
        k_agg_mean<<<CDIV(NRr,8),256>>>(xm, adj3, off3, NRr, Arh, Arl, KT2, 0);
        k_root<<<CDIV(NRr*32,256),256>>>(xr, Arh, Arl, NRr, KT2, 128);

        // fused m-target (agg + GEMM + bias + relu in one kernel)
        k_fusedM<<<CDIV(NMm,128),256,SMEM_FUSED_BYTES>>>(
            xs, adj0, off0, xr, adj2, off2, xm, adj4, off4, dinvF,
            adj5, off5, dinvR, Bmh, Bml, biasM, XMo, NMm);

        // s/r GEMMs
        k_mma2<<<CDIV(NSs,128),256,SMEM_MMA2_BYTES>>>(Ash, Asl, Bsh, Bsl, bl1, XSo, NSs, KT2);
        k_mma2<<<CDIV(NRr,128),256,SMEM_MMA2_BYTES>>>(Arh, Arl, Brh, Brl, bl3, XRo, NRr, KT2);
    }

    const float* XSf = XS + (size_t)1*NSs*HH;
    const float* XMf = XM + (size_t)1*NMm*HH;
    const float* XRf = XR + (size_t)1*NRr*HH;
    k_pred<<<CDIV(LL,8),256>>>(XSf, XMf, XRf, lbl_s, lbl_m, lbl_r, out);

    (void)in_sizes; (void)n_in; (void)out_size;
}

// round 15
// speedup vs baseline: 1.8213x; 1.8213x over previous
#include <cuda_runtime.h>
#include <cuda_bf16.h>
#include <cstdint>

#define NSs   5000
#define NMm   100000
#define NRr   2000
#define HH    128
#define ESM   2000000
#define ERM   1000000
#define ESIM  2000000
#define LL    500000
#define KTM   640      // fused K for mrna target
#define KT2   256      // fused K for srna/rbp targets

#define CDIV(a,b) (((a)+(b)-1)/(b))

// ---------------- device scratch ----------------
static __device__ float g_XS[2][NSs*HH];
static __device__ float g_XM[2][NMm*HH];
static __device__ float g_XR[2][NRr*HH];

static __device__ __nv_bfloat16 g_Amh[(size_t)NMm*KTM];
static __device__ __nv_bfloat16 g_Aml[(size_t)NMm*KTM];
static __device__ __nv_bfloat16 g_Ash[(size_t)NSs*KT2];
static __device__ __nv_bfloat16 g_Asl[(size_t)NSs*KT2];
static __device__ __nv_bfloat16 g_Arh[(size_t)NRr*KT2];
static __device__ __nv_bfloat16 g_Arl[(size_t)NRr*KT2];

static __device__ __nv_bfloat16 g_Bmh[HH*KTM], g_Bml[HH*KTM];
static __device__ __nv_bfloat16 g_Bsh[HH*KT2], g_Bsl[HH*KT2];
static __device__ __nv_bfloat16 g_Brh[HH*KT2], g_Brl[HH*KT2];
static __device__ float g_biasM[HH];

static __device__ int g_adj0[ESM];
static __device__ int g_adj1[ESM];
static __device__ int g_adj2[ERM];
static __device__ int g_adj3[ERM];
static __device__ int g_adj4[ESIM];
static __device__ int g_adj5[ESIM];

static __device__ int g_off0[NMm+1];
static __device__ int g_off1[NSs+1];
static __device__ int g_off2[NMm+1];
static __device__ int g_off3[NRr+1];
static __device__ int g_off4[NMm+1];
static __device__ int g_off5[NMm+1];

// batched CSR scratch: private cnt/incl/cur region per build
#define CNT_O0 0
#define CNT_O1 (NMm)
#define CNT_O2 (NMm+NSs)
#define CNT_O3 (2*NMm+NSs)
#define CNT_O4 (2*NMm+NSs+NRr)
#define CNT_O5 (3*NMm+NSs+NRr)
#define CNT_TOT (4*NMm+NSs+NRr)
static __device__ int g_cnt6[CNT_TOT];
static __device__ int g_incl6[CNT_TOT];
static __device__ int g_cur6[CNT_TOT];
static __device__ int g_bsums6[6*1024];

static __device__ float g_dinvF[NMm];
static __device__ float g_dinvR[NMm];

// ---------------- bf16 hi/lo split helper ----------------
__device__ __forceinline__ void split_store4(float a, float b, float c, float d,
                                             __nv_bfloat16* oh, __nv_bfloat16* ol){
    __nv_bfloat16 ha = __float2bfloat16(a), hb = __float2bfloat16(b),
                  hc = __float2bfloat16(c), hd = __float2bfloat16(d);
    __nv_bfloat16 la = __float2bfloat16(a - __bfloat162float(ha));
    __nv_bfloat16 lb = __float2bfloat16(b - __bfloat162float(hb));
    __nv_bfloat16 lc = __float2bfloat16(c - __bfloat162float(hc));
    __nv_bfloat16 ld = __float2bfloat16(d - __bfloat162float(hd));
    ushort4 H; H.x = __bfloat16_as_ushort(ha); H.y = __bfloat16_as_ushort(hb);
               H.z = __bfloat16_as_ushort(hc); H.w = __bfloat16_as_ushort(hd);
    ushort4 L; L.x = __bfloat16_as_ushort(la); L.y = __bfloat16_as_ushort(lb);
               L.z = __bfloat16_as_ushort(lc); L.w = __bfloat16_as_ushort(ld);
    *(ushort4*)oh = H;
    *(ushort4*)ol = L;
}

// ================= batched CSR build =================
#define NB_E2M CDIV(ESM,256)
#define NB_E1M CDIV(ERM,256)
#define EDGE_BLKS (4*NB_E2M + 2*NB_E1M)
#define SB_NM CDIV(NMm,1024)
#define SB_NS CDIV(NSs,1024)
#define SB_NR CDIV(NRr,1024)
#define SCAN_BLKS (4*SB_NM + SB_NS + SB_NR)

struct CsrArgs {
    const int *k0,*k1,*k2,*k3,*k4,*k5;
    const int *v0,*v1,*v2,*v3,*v4,*v5;
};
struct OffPtrs  { int *o0,*o1,*o2,*o3,*o4,*o5; };
struct AdjPtrs  { int *a0,*a1,*a2,*a3,*a4,*a5; };

__device__ __forceinline__ void seg6_edges(int b, int& seg, int& lb){
    if      (b < NB_E2M)                      { seg=0; lb=b; }
    else if (b < 2*NB_E2M)                    { seg=1; lb=b-NB_E2M; }
    else if (b < 2*NB_E2M+NB_E1M)             { seg=2; lb=b-2*NB_E2M; }
    else if (b < 2*NB_E2M+2*NB_E1M)           { seg=3; lb=b-2*NB_E2M-NB_E1M; }
    else if (b < 3*NB_E2M+2*NB_E1M)           { seg=4; lb=b-2*NB_E2M-2*NB_E1M; }
    else                                      { seg=5; lb=b-3*NB_E2M-2*NB_E1M; }
}
__device__ __forceinline__ void seg6_scan(int b, int& seg, int& lb){
    if      (b < SB_NM)                      { seg=0; lb=b; }
    else if (b < SB_NM+SB_NS)                { seg=1; lb=b-SB_NM; }
    else if (b < 2*SB_NM+SB_NS)              { seg=2; lb=b-SB_NM-SB_NS; }
    else if (b < 2*SB_NM+SB_NS+SB_NR)        { seg=3; lb=b-2*SB_NM-SB_NS; }
    else if (b < 3*SB_NM+SB_NS+SB_NR)        { seg=4; lb=b-2*SB_NM-SB_NS-SB_NR; }
    else                                     { seg=5; lb=b-3*SB_NM-SB_NS-SB_NR; }
}
__device__ __forceinline__ void seg_scan_params(int seg, int& n, int& co){
    switch(seg){
        case 0: n=NMm; co=CNT_O0; break;
        case 1: n=NSs; co=CNT_O1; break;
        case 2: n=NMm; co=CNT_O2; break;
        case 3: n=NRr; co=CNT_O3; break;
        case 4: n=NMm; co=CNT_O4; break;
        default:n=NMm; co=CNT_O5; break;
    }
}

__global__ void k_zero_i(int* p, int n){
    int i = blockIdx.x*blockDim.x + threadIdx.x;
    if (i < n) p[i] = 0;
}
__global__ void k_count_all(CsrArgs a, int* __restrict__ cnt){
    int seg, lb; seg6_edges(blockIdx.x, seg, lb);
    int i = lb*256 + threadIdx.x;
    const int* key; int e, co;
    switch(seg){
        case 0: key=a.k0; e=ESM;  co=CNT_O0; break;
        case 1: key=a.k1; e=ESM;  co=CNT_O1; break;
        case 2: key=a.k2; e=ERM;  co=CNT_O2; break;
        case 3: key=a.k3; e=ERM;  co=CNT_O3; break;
        case 4: key=a.k4; e=ESIM; co=CNT_O4; break;
        default:key=a.k5; e=ESIM; co=CNT_O5; break;
    }
    if (i < e) atomicAdd(&cnt[co + key[i]], 1);
}
__global__ void k_scan1_all(const int* __restrict__ cnt, int* __restrict__ incl,
                            int* __restrict__ bsums){
    __shared__ int sh[1024];
    int seg, lb; seg6_scan(blockIdx.x, seg, lb);
    int n, co; seg_scan_params(seg, n, co);
    int i = lb*1024 + threadIdx.x;
    sh[threadIdx.x] = (i < n) ? cnt[co + i] : 0;
    __syncthreads();
    for (int d = 1; d < 1024; d <<= 1){
        int t = (threadIdx.x >= d) ? sh[threadIdx.x - d] : 0;
        __syncthreads();
        sh[threadIdx.x] += t;
        __syncthreads();
    }
    if (i < n) incl[co + i] = sh[threadIdx.x];
    if (threadIdx.x == 1023) bsums[seg*1024 + lb] = sh[1023];
}
__global__ void k_scan2_all(int* bsums){
    __shared__ int sh[1024];
    int seg = blockIdx.x;
    int n, co; seg_scan_params(seg, n, co);
    int nb = CDIV(n, 1024);
    sh[threadIdx.x] = (threadIdx.x < nb) ? bsums[seg*1024 + threadIdx.x] : 0;
    __syncthreads();
    for (int d = 1; d < 1024; d <<= 1){
        int t = (threadIdx.x >= d) ? sh[threadIdx.x - d] : 0;
        __syncthreads();
        sh[threadIdx.x] += t;
        __syncthreads();
    }
    if (threadIdx.x < nb) bsums[seg*1024 + threadIdx.x] = sh[threadIdx.x];
}
__global__ void k_scan3_all(const int* __restrict__ incl, const int* __restrict__ bsums,
                            const int* __restrict__ cnt, OffPtrs op, int* __restrict__ cur){
    int seg, lb; seg6_scan(blockIdx.x, seg, lb);
    int n, co; seg_scan_params(seg, n, co);
    int* off;
    switch(seg){ case 0: off=op.o0; break; case 1: off=op.o1; break; case 2: off=op.o2; break;
                 case 3: off=op.o3; break; case 4: off=op.o4; break; default: off=op.o5; break; }
    int i = lb*1024 + threadIdx.x;
    if (i < n){
        int add = lb ? bsums[seg*1024 + lb - 1] : 0;
        int v = incl[co + i] + add;
        off[i+1] = v;
        if (i == 0) off[0] = 0;
        cur[co + i] = v - cnt[co + i];
    }
}
__global__ void k_fill_all(CsrArgs a, AdjPtrs ap, int* __restrict__ cur){
    int seg, lb; seg6_edges(blockIdx.x, seg, lb);
    int i = lb*256 + threadIdx.x;
    const int *key, *val; int e, co; int* adj;
    switch(seg){
        case 0: key=a.k0; val=a.v0; e=ESM;  co=CNT_O0; adj=ap.a0; break;
        case 1: key=a.k1; val=a.v1; e=ESM;  co=CNT_O1; adj=ap.a1; break;
        case 2: key=a.k2; val=a.v2; e=ERM;  co=CNT_O2; adj=ap.a2; break;
        case 3: key=a.k3; val=a.v3; e=ERM;  co=CNT_O3; adj=ap.a3; break;
        case 4: key=a.k4; val=a.v4; e=ESIM; co=CNT_O4; adj=ap.a4; break;
        default:key=a.k5; val=a.v5; e=ESIM; co=CNT_O5; adj=ap.a5; break;
    }
    if (i < e){
        int p = atomicAdd(&cur[co + key[i]], 1);
        adj[p] = val[i];
    }
}
__global__ void k_dinv2(const int* __restrict__ off4, const int* __restrict__ off5,
                        float* __restrict__ dF, float* __restrict__ dR){
    int i = blockIdx.x*blockDim.x + threadIdx.x;
    if (i < NMm){
        dF[i] = rsqrtf((float)(off4[i+1] - off4[i] + 1));
        dR[i] = rsqrtf((float)(off5[i+1] - off5[i] + 1));
    }
}

// ---------------- weight-stack / bias builders ----------------
// m-B layout: [Wl0 | Wl2 | gW0 | gW1 | Wsum] (root last; matches agg col offsets)
__global__ void k_buildB_m(const float* __restrict__ Wl0, const float* __restrict__ Wl2,
                           const float* __restrict__ Wr0, const float* __restrict__ Wr2,
                           const float* __restrict__ gW0, const float* __restrict__ gW1,
                           __nv_bfloat16* __restrict__ oh, __nv_bfloat16* __restrict__ ol){
    int i = blockIdx.x*blockDim.x + threadIdx.x;
    if (i >= HH*KTM) return;
    int n = i / KTM, k = i % KTM;
    int sl = k >> 7, kk = k & 127;
    float v;
    if      (sl == 0) v = Wl0[kk*HH + n];
    else if (sl == 1) v = Wl2[kk*HH + n];
    else if (sl == 2) v = gW0[kk*HH + n];
    else if (sl == 3) v = gW1[kk*HH + n];
    else              v = Wr0[kk*HH + n] + Wr2[kk*HH + n];
    __nv_bfloat16 h = __float2bfloat16(v);
    oh[i] = h;
    ol[i] = __float2bfloat16(v - __bfloat162float(h));
}
__global__ void k_buildB_2(const float* __restrict__ Wa, const float* __restrict__ Wb,
                           __nv_bfloat16* __restrict__ oh, __nv_bfloat16* __restrict__ ol){
    int i = blockIdx.x*blockDim.x + threadIdx.x;
    if (i >= HH*KT2) return;
    int n = i / KT2, k = i % KT2;
    float v = (k < 128) ? Wa[(k&127)*HH + n] : Wb[(k&127)*HH + n];
    __nv_bfloat16 h = __float2bfloat16(v);
    oh[i] = h;
    ol[i] = __float2bfloat16(v - __bfloat162float(h));
}
__global__ void k_bias4(const float* a, const float* b, const float* c, const float* d, float* o){
    int i = threadIdx.x;
    if (i < HH) o[i] = a[i] + b[i] + c[i] + d[i];
}

// ---------------- aggregation: warp per dst, fp32 gather (R4-exact) ----------------
__global__ void k_agg_mean(const float* __restrict__ X, const int* __restrict__ adj,
                           const int* __restrict__ off, int n,
                           __nv_bfloat16* __restrict__ oh, __nv_bfloat16* __restrict__ ol,
                           int Kt, int coloff){
    int w = (blockIdx.x*blockDim.x + threadIdx.x) >> 5;
    int lane = threadIdx.x & 31;
    if (w >= n) return;
    int beg = off[w], end = off[w+1];
    int c = lane * 4;
    float4 acc = make_float4(0.f, 0.f, 0.f, 0.f);
    int j = beg;
    for (; j + 4 <= end; j += 4){
        int n0 = adj[j], n1 = adj[j+1], n2 = adj[j+2], n3 = adj[j+3];
        float4 v0 = *(const float4*)(X + (size_t)n0*HH + c);
        float4 v1 = *(const float4*)(X + (size_t)n1*HH + c);
        float4 v2 = *(const float4*)(X + (size_t)n2*HH + c);
        float4 v3 = *(const float4*)(X + (size_t)n3*HH + c);
        acc.x += v0.x + v1.x + v2.x + v3.x;
        acc.y += v0.y + v1.y + v2.y + v3.y;
        acc.z += v0.z + v1.z + v2.z + v3.z;
        acc.w += v0.w + v1.w + v2.w + v3.w;
    }
    for (; j < end; j++){
        int nb = adj[j];
        float4 v = *(const float4*)(X + (size_t)nb*HH + c);
        acc.x += v.x; acc.y += v.y; acc.z += v.z; acc.w += v.w;
    }
    int cnt = end - beg;
    float inv = 1.f / (float)(cnt > 1 ? cnt : 1);
    size_t base = (size_t)w*Kt + coloff + c;
    split_store4(acc.x*inv, acc.y*inv, acc.z*inv, acc.w*inv, oh + base, ol + base);
}

__global__ void k_agg_gcn(const float* __restrict__ X, const int* __restrict__ adj,
                          const int* __restrict__ off, const float* __restrict__ dinv,
                          int n, __nv_bfloat16* __restrict__ oh, __nv_bfloat16* __restrict__ ol,
                          int Kt, int coloff){
    int w = (blockIdx.x*blockDim.x + threadIdx.x) >> 5;
    int lane = threadIdx.x & 31;
    if (w >= n) return;
    int beg = off[w], end = off[w+1];
    int c = lane * 4;
    float wd = dinv[w];
    float4 xx = *(const float4*)(X + (size_t)w*HH + c);
    float ws = wd * wd;
    float4 acc = make_float4(ws*xx.x, ws*xx.y, ws*xx.z, ws*xx.w);
    int j = beg;
    for (; j + 4 <= end; j += 4){
        int n0 = adj[j], n1 = adj[j+1], n2 = adj[j+2], n3 = adj[j+3];
        float w0 = wd * dinv[n0], w1 = wd * dinv[n1], w2 = wd * dinv[n2], w3 = wd * dinv[n3];
        float4 v0 = *(const float4*)(X + (size_t)n0*HH + c);
        float4 v1 = *(const float4*)(X + (size_t)n1*HH + c);
        float4 v2 = *(const float4*)(X + (size_t)n2*HH + c);
        float4 v3 = *(const float4*)(X + (size_t)n3*HH + c);
        acc.x += w0*v0.x + w1*v1.x + w2*v2.x + w3*v3.x;
        acc.y += w0*v0.y + w1*v1.y + w2*v2.y + w3*v3.y;
        acc.z += w0*v0.z + w1*v1.z + w2*v2.z + w3*v3.z;
        acc.w += w0*v0.w + w1*v1.w + w2*v2.w + w3*v3.w;
    }
    for (; j < end; j++){
        int nb = adj[j];
        float wn = wd * dinv[nb];
        float4 v = *(const float4*)(X + (size_t)nb*HH + c);
        acc.x += wn*v.x; acc.y += wn*v.y; acc.z += wn*v.z; acc.w += wn*v.w;
    }
    size_t base = (size_t)w*Kt + coloff + c;
    split_store4(acc.x, acc.y, acc.z, acc.w, oh + base, ol + base);
}

__global__ void k_root(const float* __restrict__ X,
                       __nv_bfloat16* __restrict__ oh, __nv_bfloat16* __restrict__ ol,
                       int n, int Kt, int coloff){
    int idx = blockIdx.x*blockDim.x + threadIdx.x;
    if (idx >= n*32) return;
    int w = idx >> 5, c4 = (idx & 31) * 4;
    float4 v = *(const float4*)(X + (size_t)w*HH + c4);
    size_t base = (size_t)w*Kt + coloff + c4;
    split_store4(v.x, v.y, v.z, v.w, oh + base, ol + base);
}

// ---------------- HMMA GEMM: double-buffered cp.async pipeline (R12-exact) ----------------
#define LDSB 72
#define SM_BUF (128*LDSB)
#define SM_BUF_BYTES (SM_BUF*2)
#define STAGE_BYTES (4*SM_BUF_BYTES)
#define SMEM_MMA_BYTES (2*STAGE_BYTES)

__device__ __forceinline__ uint32_t smem_u32(const void* p){
    uint32_t a;
    asm("{ .reg .u64 t; cvta.to.shared.u64 t, %1; cvt.u32.u64 %0, t; }" : "=r"(a) : "l"(p));
    return a;
}
#define CP_ASYNC16(dst, src, sz) \
    asm volatile("cp.async.cg.shared.global [%0], [%1], 16, %2;" :: "r"(dst), "l"(src), "r"(sz))
#define CP_COMMIT() asm volatile("cp.async.commit_group;" ::: "memory")
#define CP_WAIT1()  asm volatile("cp.async.wait_group 1;" ::: "memory")
#define CP_WAIT0()  asm volatile("cp.async.wait_group 0;" ::: "memory")

__device__ __forceinline__ void mma_bf16(float* c, const uint32_t* a, const uint32_t* b){
    asm volatile(
        "mma.sync.aligned.m16n8k16.row.col.f32.bf16.bf16.f32 "
        "{%0,%1,%2,%3}, {%4,%5,%6,%7}, {%8,%9}, {%0,%1,%2,%3};"
        : "+f"(c[0]), "+f"(c[1]), "+f"(c[2]), "+f"(c[3])
        : "r"(a[0]), "r"(a[1]), "r"(a[2]), "r"(a[3]), "r"(b[0]), "r"(b[1]));
}

__global__ void __launch_bounds__(256)
k_mma(const __nv_bfloat16* __restrict__ Ah, const __nv_bfloat16* __restrict__ Al,
      const __nv_bfloat16* __restrict__ Bh, const __nv_bfloat16* __restrict__ Bl,
      const float* __restrict__ bias, float* __restrict__ Xout, int n, int Ktot)
{
    extern __shared__ char smem[];
    const uint32_t sbase = smem_u32(smem);
    const int tid  = threadIdx.x;
    const int wid  = tid >> 5;
    const int lane = tid & 31;
    const int g    = lane >> 2;
    const int t2   = lane & 3;
    const int warp_m = wid & 1;
    const int warp_n = wid >> 1;
    const int row0 = blockIdx.x * 128;
    const int NC = Ktot >> 6;

    float acc[4][4][4];
    #pragma unroll
    for (int mt = 0; mt < 4; mt++)
        #pragma unroll
        for (int nt = 0; nt < 4; nt++)
            #pragma unroll
            for (int r = 0; r < 4; r++) acc[mt][nt][r] = 0.f;

    auto issue = [&](int cch){
        const int stg = cch & 1;
        const uint32_t stb = sbase + stg*STAGE_BYTES;
        const int kc = cch << 6;
        #pragma unroll
        for (int j = 0; j < 4; j++){
            int idx = tid + j*256;
            int row = idx >> 3, c8 = idx & 7;
            uint32_t soff = (uint32_t)(row*LDSB + c8*8) * 2;
            int gr = row0 + row;
            uint32_t sza = (gr < n) ? 16u : 0u;
            CP_ASYNC16(stb + 0*SM_BUF_BYTES + soff, (const char*)(Ah + (size_t)gr*Ktot + kc + c8*8), sza);
            CP_ASYNC16(stb + 1*SM_BUF_BYTES + soff, (const char*)(Al + (size_t)gr*Ktot + kc + c8*8), sza);
            CP_ASYNC16(stb + 2*SM_BUF_BYTES + soff, (const char*)(Bh + (size_t)row*Ktot + kc + c8*8), 16u);
            CP_ASYNC16(stb + 3*SM_BUF_BYTES + soff, (const char*)(Bl + (size_t)row*Ktot + kc + c8*8), 16u);
        }
    };

    issue(0); CP_COMMIT();
    if (NC > 1){ issue(1); CP_COMMIT(); }

    for (int cch = 0; cch < NC; cch++){
        if (cch + 1 < NC) CP_WAIT1(); else CP_WAIT0();
        __syncthreads();

        const int stg = cch & 1;
        const __nv_bfloat16* sAh = (const __nv_bfloat16*)(smem + stg*STAGE_BYTES);
        const __nv_bfloat16* sAl = sAh + SM_BUF;
        const __nv_bfloat16* sBh = sAh + 2*SM_BUF;
        const __nv_bfloat16* sBl = sAh + 3*SM_BUF;

        #pragma unroll
        for (int ks = 0; ks < 4; ks++){
            const int k0 = ks * 16;
            uint32_t afh[4][4], afl[4][4], bfh[4][2], bfl[4][2];
            #pragma unroll
            for (int mt = 0; mt < 4; mt++){
                int rbase = warp_m*64 + mt*16;
                #pragma unroll
                for (int r = 0; r < 4; r++){
                    int row = rbase + g + (r & 1)*8;
                    int col = k0 + t2*2 + (r >> 1)*8;
                    afh[mt][r] = *(const uint32_t*)(sAh + row*LDSB + col);
                    afl[mt][r] = *(const uint32_t*)(sAl + row*LDSB + col);
                }
            }
            #pragma unroll
            for (int nt = 0; nt < 4; nt++){
                int nrow = warp_n*32 + nt*8 + g;
                #pragma unroll
                for (int r = 0; r < 2; r++){
                    int col = k0 + t2*2 + r*8;
                    bfh[nt][r] = *(const uint32_t*)(sBh + nrow*LDSB + col);
                    bfl[nt][r] = *(const uint32_t*)(sBl + nrow*LDSB + col);
                }
            }
            #pragma unroll
            for (int mt = 0; mt < 4; mt++)
                #pragma unroll
                for (int nt = 0; nt < 4; nt++){
                    mma_bf16(acc[mt][nt], afh[mt], bfh[nt]);
                    mma_bf16(acc[mt][nt], afh[mt], bfl[nt]);
                    mma_bf16(acc[mt][nt], afl[mt], bfh[nt]);
                }
        }
        __syncthreads();
        if (cch + 2 < NC){ issue(cch + 2); CP_COMMIT(); }
    }

    #pragma unroll
    for (int mt = 0; mt < 4; mt++){
        #pragma unroll
        for (int nt = 0; nt < 4; nt++){
            int col = warp_n*32 + nt*8 + t2*2;
            float b0 = bias[col], b1 = bias[col+1];
            int r0 = row0 + warp_m*64 + mt*16 + g;
            if (r0 < n){
                float2 o;
                o.x = fmaxf(acc[mt][nt][0] + b0, 0.f);
                o.y = fmaxf(acc[mt][nt][1] + b1, 0.f);
                *(float2*)(Xout + (size_t)r0*HH + col) = o;
            }
            int r1 = r0 + 8;
            if (r1 < n){
                float2 o;
                o.x = fmaxf(acc[mt][nt][2] + b0, 0.f);
                o.y = fmaxf(acc[mt][nt][3] + b1, 0.f);
                *(float2*)(Xout + (size_t)r1*HH + col) = o;
            }
        }
    }
}

// ---------------- fused readout ----------------
__global__ void k_pred(const float* __restrict__ XS, const float* __restrict__ XM,
                       const float* __restrict__ XR,
                       const int* __restrict__ ls, const int* __restrict__ lm,
                       const int* __restrict__ lr, float* __restrict__ out){
    int w = (blockIdx.x*blockDim.x + threadIdx.x) >> 5;
    int lane = threadIdx.x & 31;
    if (w >= LL) return;
    const float* m = XM + (size_t)lm[w]*HH;
    const float* s = XS + (size_t)ls[w]*HH;
    const float* r = XR + (size_t)lr[w]*HH;
    float4 vm = *(const float4*)(m + lane*4);
    float4 vs = *(const float4*)(s + lane*4);
    float4 vr = *(const float4*)(r + lane*4);
    float ds = vs.x*vm.x + vs.y*vm.y + vs.z*vm.z + vs.w*vm.w;
    float dr = vr.x*vm.x + vr.y*vm.y + vr.z*vm.z + vr.w*vm.w;
    #pragma unroll
    for (int d = 16; d; d >>= 1){
        ds += __shfl_xor_sync(0xffffffffu, ds, d);
        dr += __shfl_xor_sync(0xffffffffu, dr, d);
    }
    if (lane == 0){ out[w] = ds; out[LL + w] = dr; }
}

// ---------------- host ----------------
static inline void* symaddr(const void* sym){
    void* p = nullptr;
    cudaGetSymbolAddress(&p, sym);
    return p;
}

extern "C" void kernel_launch(void* const* d_in, const int* in_sizes, int n_in,
                              void* d_out, int out_size){
    const float* emb_s  = (const float*)d_in[0];
    const float* emb_m  = (const float*)d_in[1];
    const float* emb_r  = (const float*)d_in[2];
    const float* sageWl = (const float*)d_in[3];
    const float* sageBl = (const float*)d_in[4];
    const float* sageWr = (const float*)d_in[5];
    const float* gcnW   = (const float*)d_in[6];
    const float* gcnB   = (const float*)d_in[7];
    const int* src_sm   = (const int*)d_in[8];
    const int* dst_sm   = (const int*)d_in[9];
    const int* src_rm   = (const int*)d_in[10];
    const int* dst_rm   = (const int*)d_in[11];
    const int* src_sim  = (const int*)d_in[12];
    const int* dst_sim  = (const int*)d_in[13];
    const int* lbl_s    = (const int*)d_in[14];
    const int* lbl_m    = (const int*)d_in[15];
    const int* lbl_r    = (const int*)d_in[16];
    float* out = (float*)d_out;

    cudaFuncSetAttribute(k_mma, cudaFuncAttributeMaxDynamicSharedMemorySize, SMEM_MMA_BYTES);

    float* XS = (float*)symaddr(g_XS);
    float* XM = (float*)symaddr(g_XM);
    float* XR = (float*)symaddr(g_XR);
    __nv_bfloat16* Amh = (__nv_bfloat16*)symaddr(g_Amh);
    __nv_bfloat16* Aml = (__nv_bfloat16*)symaddr(g_Aml);
    __nv_bfloat16* Ash = (__nv_bfloat16*)symaddr(g_Ash);
    __nv_bfloat16* Asl = (__nv_bfloat16*)symaddr(g_Asl);
    __nv_bfloat16* Arh = (__nv_bfloat16*)symaddr(g_Arh);
    __nv_bfloat16* Arl = (__nv_bfloat16*)symaddr(g_Arl);
    __nv_bfloat16* Bmh = (__nv_bfloat16*)symaddr(g_Bmh);
    __nv_bfloat16* Bml = (__nv_bfloat16*)symaddr(g_Bml);
    __nv_bfloat16* Bsh = (__nv_bfloat16*)symaddr(g_Bsh);
    __nv_bfloat16* Bsl = (__nv_bfloat16*)symaddr(g_Bsl);
    __nv_bfloat16* Brh = (__nv_bfloat16*)symaddr(g_Brh);
    __nv_bfloat16* Brl = (__nv_bfloat16*)symaddr(g_Brl);
    float* biasM = (float*)symaddr(g_biasM);
    int* adj0 = (int*)symaddr(g_adj0);
    int* adj1 = (int*)symaddr(g_adj1);
    int* adj2 = (int*)symaddr(g_adj2);
    int* adj3 = (int*)symaddr(g_adj3);
    int* adj4 = (int*)symaddr(g_adj4);
    int* adj5 = (int*)symaddr(g_adj5);
    int* off0 = (int*)symaddr(g_off0);
    int* off1 = (int*)symaddr(g_off1);
    int* off2 = (int*)symaddr(g_off2);
    int* off3 = (int*)symaddr(g_off3);
    int* off4 = (int*)symaddr(g_off4);
    int* off5 = (int*)symaddr(g_off5);
    int* cnt6  = (int*)symaddr(g_cnt6);
    int* incl6 = (int*)symaddr(g_incl6);
    int* cur6  = (int*)symaddr(g_cur6);
    int* bsum6 = (int*)symaddr(g_bsums6);
    float* dinvF = (float*)symaddr(g_dinvF);
    float* dinvR = (float*)symaddr(g_dinvR);

    // ---- batched CSR build ----
    CsrArgs ca;
    ca.k0 = dst_sm;  ca.v0 = src_sm;
    ca.k1 = src_sm;  ca.v1 = dst_sm;
    ca.k2 = dst_rm;  ca.v2 = src_rm;
    ca.k3 = src_rm;  ca.v3 = dst_rm;
    ca.k4 = dst_sim; ca.v4 = src_sim;
    ca.k5 = src_sim; ca.v5 = dst_sim;
    OffPtrs op = { off0, off1, off2, off3, off4, off5 };
    AdjPtrs ap = { adj0, adj1, adj2, adj3, adj4, adj5 };

    k_zero_i<<<CDIV(CNT_TOT,256),256>>>(cnt6, CNT_TOT);
    k_count_all<<<EDGE_BLKS,256>>>(ca, cnt6);
    k_scan1_all<<<SCAN_BLKS,1024>>>(cnt6, incl6, bsum6);
    k_scan2_all<<<6,1024>>>(bsum6);
    k_scan3_all<<<SCAN_BLKS,1024>>>(incl6, bsum6, cnt6, op, cur6);
    k_fill_all<<<EDGE_BLKS,256>>>(ca, ap, cur6);
    k_dinv2<<<CDIV(NMm,256),256>>>(off4, off5, dinvF, dinvR);

    const int HW = HH*HH;

    for (int l = 0; l < 2; l++){
        const float* xs = l ? XS : emb_s;
        const float* xm = l ? XM : emb_m;
        const float* xr = l ? XR : emb_r;
        float* XSo = XS + (size_t)l*NSs*HH;
        float* XMo = XM + (size_t)l*NMm*HH;
        float* XRo = XR + (size_t)l*NRr*HH;

        const float* Wl0 = sageWl + (size_t)(l*4+0)*HW;
        const float* Wl1 = sageWl + (size_t)(l*4+1)*HW;
        const float* Wl2 = sageWl + (size_t)(l*4+2)*HW;
        const float* Wl3 = sageWl + (size_t)(l*4+3)*HW;
        const float* bl0 = sageBl + (size_t)(l*4+0)*HH;
        const float* bl1 = sageBl + (size_t)(l*4+1)*HH;
        const float* bl2 = sageBl + (size_t)(l*4+2)*HH;
        const float* bl3 = sageBl + (size_t)(l*4+3)*HH;
        const float* Wr0 = sageWr + (size_t)(l*4+0)*HW;
        const float* Wr1 = sageWr + (size_t)(l*4+1)*HW;
        const float* Wr2 = sageWr + (size_t)(l*4+2)*HW;
        const float* Wr3 = sageWr + (size_t)(l*4+3)*HW;
        const float* gW0 = gcnW + (size_t)(l*2+0)*HW;
        const float* gW1 = gcnW + (size_t)(l*2+1)*HW;
        const float* gb0 = gcnB + (size_t)(l*2+0)*HH;
        const float* gb1 = gcnB + (size_t)(l*2+1)*HH;

        // weight stacks + fused bias
        k_buildB_m<<<CDIV(HH*KTM,256),256>>>(Wl0, Wl2, Wr0, Wr2, gW0, gW1, Bmh, Bml);
        k_buildB_2<<<CDIV(HH*KT2,256),256>>>(Wl1, Wr1, Bsh, Bsl);
        k_buildB_2<<<CDIV(HH*KT2,256),256>>>(Wl3, Wr3, Brh, Brl);
        k_bias4<<<1,128>>>(bl0, bl2, gb0, gb1, biasM);

        // m-target A slices: [mean_s | mean_r | gcn_fwd | gcn_rev | root]
        k_agg_mean<<<CDIV(NMm,8),256>>>(xs, adj0, off0, NMm, Amh, Aml, KTM, 0);
        k_agg_mean<<<CDIV(NMm,8),256>>>(xr, adj2, off2, NMm, Amh, Aml, KTM, 128);
        k_agg_gcn<<<CDIV(NMm,8),256>>>(xm, adj4, off4, dinvF, NMm, Amh, Aml, KTM, 256);
        k_agg_gcn<<<CDIV(NMm,8),256>>>(xm, adj5, off5, dinvR, NMm, Amh, Aml, KTM, 384);
        k_root<<<CDIV(NMm*32,256),256>>>(xm, Amh, Aml, NMm, KTM, 512);
        // s-target: [mean from m | root]
        k_agg_mean<<<CDIV(NSs,8),256>>>(xm, adj1, off1, NSs, Ash, Asl, KT2, 0);
        k_root<<<CDIV(NSs*32,256),256>>>(xs, Ash, Asl, NSs, KT2, 128);
        // r-target
        k_agg_mean<<<CDIV(NRr,8),256>>>(xm, adj3, off3, NRr, Arh, Arl, KT2, 0);
        k_root<<<CDIV(NRr*32,256),256>>>(xr, Arh, Arl, NRr, KT2, 128);

        // pipelined HMMA GEMMs (bias+relu fused)
        k_mma<<<CDIV(NMm,128),256,SMEM_MMA_BYTES>>>(Amh, Aml, Bmh, Bml, biasM, XMo, NMm, KTM);
        k_mma<<<CDIV(NSs,128),256,SMEM_MMA_BYTES>>>(Ash, Asl, Bsh, Bsl, bl1, XSo, NSs, KT2);
        k_mma<<<CDIV(NRr,128),256,SMEM_MMA_BYTES>>>(Arh, Arl, Brh, Brl, bl3, XRo, NRr, KT2);
    }

    const float* XSf = XS + (size_t)1*NSs*HH;
    const float* XMf = XM + (size_t)1*NMm*HH;
    const float* XRf = XR + (size_t)1*NRr*HH;
    k_pred<<<CDIV(LL,8),256>>>(XSf, XMf, XRf, lbl_s, lbl_m, lbl_r, out);

    (void)in_sizes; (void)n_in; (void)out_size;
}

// round 16
// speedup vs baseline: 1.8420x; 1.0113x over previous
#include <cuda_runtime.h>
#include <cuda_bf16.h>
#include <cstdint>

#define NSs   5000
#define NMm   100000
#define NRr   2000
#define HH    128
#define ESM   2000000
#define ERM   1000000
#define ESIM  2000000
#define LL    500000
#define KTM   640
#define KT2   256

#define CDIV(a,b) (((a)+(b)-1)/(b))

// ---------------- device scratch ----------------
static __device__ float g_XS[2][NSs*HH];
static __device__ float g_XM[2][NMm*HH];
static __device__ float g_XR[2][NRr*HH];

static __device__ __nv_bfloat16 g_Amh[(size_t)NMm*KTM];
static __device__ __nv_bfloat16 g_Aml[(size_t)NMm*KTM];
static __device__ __nv_bfloat16 g_Ash[(size_t)NSs*KT2];
static __device__ __nv_bfloat16 g_Asl[(size_t)NSs*KT2];
static __device__ __nv_bfloat16 g_Arh[(size_t)NRr*KT2];
static __device__ __nv_bfloat16 g_Arl[(size_t)NRr*KT2];

static __device__ __nv_bfloat16 g_Bmh[HH*KTM], g_Bml[HH*KTM];
static __device__ __nv_bfloat16 g_Bsh[HH*KT2], g_Bsl[HH*KT2];
static __device__ __nv_bfloat16 g_Brh[HH*KT2], g_Brl[HH*KT2];
static __device__ float g_biasM[HH];

static __device__ int g_adj0[ESM];
static __device__ int g_adj1[ESM];
static __device__ int g_adj2[ERM];
static __device__ int g_adj3[ERM];
static __device__ int g_adj4[ESIM];
static __device__ int g_adj5[ESIM];

static __device__ int g_off0[NMm+1];
static __device__ int g_off1[NSs+1];
static __device__ int g_off2[NMm+1];
static __device__ int g_off3[NRr+1];
static __device__ int g_off4[NMm+1];
static __device__ int g_off5[NMm+1];

#define CNT_O0 0
#define CNT_O1 (NMm)
#define CNT_O2 (NMm+NSs)
#define CNT_O3 (2*NMm+NSs)
#define CNT_O4 (2*NMm+NSs+NRr)
#define CNT_O5 (3*NMm+NSs+NRr)
#define CNT_TOT (4*NMm+NSs+NRr)
static __device__ int g_cnt6[CNT_TOT];
static __device__ int g_incl6[CNT_TOT];
static __device__ int g_cur6[CNT_TOT];
static __device__ int g_bsums6[6*1024];

static __device__ float g_dinvF[NMm];
static __device__ float g_dinvR[NMm];

// ---------------- bf16 hi/lo split helper ----------------
__device__ __forceinline__ void split_store4(float a, float b, float c, float d,
                                             __nv_bfloat16* oh, __nv_bfloat16* ol){
    __nv_bfloat16 ha = __float2bfloat16(a), hb = __float2bfloat16(b),
                  hc = __float2bfloat16(c), hd = __float2bfloat16(d);
    __nv_bfloat16 la = __float2bfloat16(a - __bfloat162float(ha));
    __nv_bfloat16 lb = __float2bfloat16(b - __bfloat162float(hb));
    __nv_bfloat16 lc = __float2bfloat16(c - __bfloat162float(hc));
    __nv_bfloat16 ld = __float2bfloat16(d - __bfloat162float(hd));
    ushort4 H; H.x = __bfloat16_as_ushort(ha); H.y = __bfloat16_as_ushort(hb);
               H.z = __bfloat16_as_ushort(hc); H.w = __bfloat16_as_ushort(hd);
    ushort4 L; L.x = __bfloat16_as_ushort(la); L.y = __bfloat16_as_ushort(lb);
               L.z = __bfloat16_as_ushort(lc); L.w = __bfloat16_as_ushort(ld);
    *(ushort4*)oh = H;
    *(ushort4*)ol = L;
}

// ================= batched CSR build (R11-proven) =================
#define NB_E2M CDIV(ESM,256)
#define NB_E1M CDIV(ERM,256)
#define EDGE_BLKS (4*NB_E2M + 2*NB_E1M)
#define SB_NM CDIV(NMm,1024)
#define SB_NS CDIV(NSs,1024)
#define SB_NR CDIV(NRr,1024)
#define SCAN_BLKS (4*SB_NM + SB_NS + SB_NR)

struct CsrArgs {
    const int *k0,*k1,*k2,*k3,*k4,*k5;
    const int *v0,*v1,*v2,*v3,*v4,*v5;
};
struct OffPtrs  { int *o0,*o1,*o2,*o3,*o4,*o5; };
struct AdjPtrs  { int *a0,*a1,*a2,*a3,*a4,*a5; };

__device__ __forceinline__ void seg6_edges(int b, int& seg, int& lb){
    if      (b < NB_E2M)                      { seg=0; lb=b; }
    else if (b < 2*NB_E2M)                    { seg=1; lb=b-NB_E2M; }
    else if (b < 2*NB_E2M+NB_E1M)             { seg=2; lb=b-2*NB_E2M; }
    else if (b < 2*NB_E2M+2*NB_E1M)           { seg=3; lb=b-2*NB_E2M-NB_E1M; }
    else if (b < 3*NB_E2M+2*NB_E1M)           { seg=4; lb=b-2*NB_E2M-2*NB_E1M; }
    else                                      { seg=5; lb=b-3*NB_E2M-2*NB_E1M; }
}
__device__ __forceinline__ void seg6_scan(int b, int& seg, int& lb){
    if      (b < SB_NM)                      { seg=0; lb=b; }
    else if (b < SB_NM+SB_NS)                { seg=1; lb=b-SB_NM; }
    else if (b < 2*SB_NM+SB_NS)              { seg=2; lb=b-SB_NM-SB_NS; }
    else if (b < 2*SB_NM+SB_NS+SB_NR)        { seg=3; lb=b-2*SB_NM-SB_NS; }
    else if (b < 3*SB_NM+SB_NS+SB_NR)        { seg=4; lb=b-2*SB_NM-SB_NS-SB_NR; }
    else                                     { seg=5; lb=b-3*SB_NM-SB_NS-SB_NR; }
}
__device__ __forceinline__ void seg_scan_params(int seg, int& n, int& co){
    switch(seg){
        case 0: n=NMm; co=CNT_O0; break;
        case 1: n=NSs; co=CNT_O1; break;
        case 2: n=NMm; co=CNT_O2; break;
        case 3: n=NRr; co=CNT_O3; break;
        case 4: n=NMm; co=CNT_O4; break;
        default:n=NMm; co=CNT_O5; break;
    }
}

__global__ void k_zero_i(int* p, int n){
    int i = blockIdx.x*blockDim.x + threadIdx.x;
    if (i < n) p[i] = 0;
}
__global__ void k_count_all(CsrArgs a, int* __restrict__ cnt){
    int seg, lb; seg6_edges(blockIdx.x, seg, lb);
    int i = lb*256 + threadIdx.x;
    const int* key; int e, co;
    switch(seg){
        case 0: key=a.k0; e=ESM;  co=CNT_O0; break;
        case 1: key=a.k1; e=ESM;  co=CNT_O1; break;
        case 2: key=a.k2; e=ERM;  co=CNT_O2; break;
        case 3: key=a.k3; e=ERM;  co=CNT_O3; break;
        case 4: key=a.k4; e=ESIM; co=CNT_O4; break;
        default:key=a.k5; e=ESIM; co=CNT_O5; break;
    }
    if (i < e) atomicAdd(&cnt[co + key[i]], 1);
}
__global__ void k_scan1_all(const int* __restrict__ cnt, int* __restrict__ incl,
                            int* __restrict__ bsums){
    __shared__ int sh[1024];
    int seg, lb; seg6_scan(blockIdx.x, seg, lb);
    int n, co; seg_scan_params(seg, n, co);
    int i = lb*1024 + threadIdx.x;
    sh[threadIdx.x] = (i < n) ? cnt[co + i] : 0;
    __syncthreads();
    for (int d = 1; d < 1024; d <<= 1){
        int t = (threadIdx.x >= d) ? sh[threadIdx.x - d] : 0;
        __syncthreads();
        sh[threadIdx.x] += t;
        __syncthreads();
    }
    if (i < n) incl[co + i] = sh[threadIdx.x];
    if (threadIdx.x == 1023) bsums[seg*1024 + lb] = sh[1023];
}
__global__ void k_scan2_all(int* bsums){
    __shared__ int sh[1024];
    int seg = blockIdx.x;
    int n, co; seg_scan_params(seg, n, co);
    int nb = CDIV(n, 1024);
    sh[threadIdx.x] = (threadIdx.x < nb) ? bsums[seg*1024 + threadIdx.x] : 0;
    __syncthreads();
    for (int d = 1; d < 1024; d <<= 1){
        int t = (threadIdx.x >= d) ? sh[threadIdx.x - d] : 0;
        __syncthreads();
        sh[threadIdx.x] += t;
        __syncthreads();
    }
    if (threadIdx.x < nb) bsums[seg*1024 + threadIdx.x] = sh[threadIdx.x];
}
__global__ void k_scan3_all(const int* __restrict__ incl, const int* __restrict__ bsums,
                            const int* __restrict__ cnt, OffPtrs op, int* __restrict__ cur){
    int seg, lb; seg6_scan(blockIdx.x, seg, lb);
    int n, co; seg_scan_params(seg, n, co);
    int* off;
    switch(seg){ case 0: off=op.o0; break; case 1: off=op.o1; break; case 2: off=op.o2; break;
                 case 3: off=op.o3; break; case 4: off=op.o4; break; default: off=op.o5; break; }
    int i = lb*1024 + threadIdx.x;
    if (i < n){
        int add = lb ? bsums[seg*1024 + lb - 1] : 0;
        int v = incl[co + i] + add;
        off[i+1] = v;
        if (i == 0) off[0] = 0;
        cur[co + i] = v - cnt[co + i];
    }
}
__global__ void k_fill_all(CsrArgs a, AdjPtrs ap, int* __restrict__ cur){
    int seg, lb; seg6_edges(blockIdx.x, seg, lb);
    int i = lb*256 + threadIdx.x;
    const int *key, *val; int e, co; int* adj;
    switch(seg){
        case 0: key=a.k0; val=a.v0; e=ESM;  co=CNT_O0; adj=ap.a0; break;
        case 1: key=a.k1; val=a.v1; e=ESM;  co=CNT_O1; adj=ap.a1; break;
        case 2: key=a.k2; val=a.v2; e=ERM;  co=CNT_O2; adj=ap.a2; break;
        case 3: key=a.k3; val=a.v3; e=ERM;  co=CNT_O3; adj=ap.a3; break;
        case 4: key=a.k4; val=a.v4; e=ESIM; co=CNT_O4; adj=ap.a4; break;
        default:key=a.k5; val=a.v5; e=ESIM; co=CNT_O5; adj=ap.a5; break;
    }
    if (i < e){
        int p = atomicAdd(&cur[co + key[i]], 1);
        adj[p] = val[i];
    }
}
__global__ void k_dinv2(const int* __restrict__ off4, const int* __restrict__ off5,
                        float* __restrict__ dF, float* __restrict__ dR){
    int i = blockIdx.x*blockDim.x + threadIdx.x;
    if (i < NMm){
        dF[i] = rsqrtf((float)(off4[i+1] - off4[i] + 1));
        dR[i] = rsqrtf((float)(off5[i+1] - off5[i] + 1));
    }
}

// ---------------- fused weight builder (one launch per layer) ----------------
struct WArgs {
    const float *Wl0,*Wl1,*Wl2,*Wl3,*bl0,*bl2,*Wr0,*Wr1,*Wr2,*Wr3,*gW0,*gW1,*gb0,*gb1;
    __nv_bfloat16 *Bmh,*Bml,*Bsh,*Bsl,*Brh,*Brl;
    float* biasM;
};
#define WB_M  CDIV(HH*KTM,256)   // 320
#define WB_2  CDIV(HH*KT2,256)   // 128
#define WB_TOT (WB_M + 2*WB_2 + 1)

__global__ void k_buildW(WArgs a){
    int b = blockIdx.x;
    if (b < WB_M){
        int i = b*256 + threadIdx.x;
        int n = i / KTM, k = i % KTM;
        int sl = k >> 7, kk = k & 127;
        float v;
        if      (sl == 0) v = a.Wl0[kk*HH + n];
        else if (sl == 1) v = a.Wl2[kk*HH + n];
        else if (sl == 2) v = a.gW0[kk*HH + n];
        else if (sl == 3) v = a.gW1[kk*HH + n];
        else              v = a.Wr0[kk*HH + n] + a.Wr2[kk*HH + n];
        __nv_bfloat16 h = __float2bfloat16(v);
        a.Bmh[i] = h;
        a.Bml[i] = __float2bfloat16(v - __bfloat162float(h));
    } else if (b < WB_M + 2*WB_2){
        int w2 = b - WB_M;
        int which = w2 / WB_2;           // 0 = s, 1 = r
        int i = (w2 % WB_2)*256 + threadIdx.x;
        int n = i / KT2, k = i % KT2;
        const float* Wa = which ? a.Wl3 : a.Wl1;
        const float* Wb = which ? a.Wr3 : a.Wr1;
        float v = (k < 128) ? Wa[(k&127)*HH + n] : Wb[(k&127)*HH + n];
        __nv_bfloat16 h = __float2bfloat16(v);
        __nv_bfloat16* oh = which ? a.Brh : a.Bsh;
        __nv_bfloat16* ol = which ? a.Brl : a.Bsl;
        oh[i] = h;
        ol[i] = __float2bfloat16(v - __bfloat162float(h));
    } else {
        int i = threadIdx.x;
        if (i < HH) a.biasM[i] = a.bl0[i] + a.bl2[i] + a.gb0[i] + a.gb1[i];
    }
}

// ---------------- aggregation bodies (R15-exact instruction streams) ----------------
__device__ __forceinline__ void agg_mean_body(const float* __restrict__ X, const int* __restrict__ adj,
                                              const int* __restrict__ off, int n,
                                              __nv_bfloat16* __restrict__ oh, __nv_bfloat16* __restrict__ ol,
                                              int Kt, int coloff, int lb){
    int w = (lb*256 + (int)threadIdx.x) >> 5;
    int lane = threadIdx.x & 31;
    if (w >= n) return;
    int beg = off[w], end = off[w+1];
    int c = lane * 4;
    float4 acc = make_float4(0.f, 0.f, 0.f, 0.f);
    int j = beg;
    for (; j + 4 <= end; j += 4){
        int n0 = adj[j], n1 = adj[j+1], n2 = adj[j+2], n3 = adj[j+3];
        float4 v0 = *(const float4*)(X + (size_t)n0*HH + c);
        float4 v1 = *(const float4*)(X + (size_t)n1*HH + c);
        float4 v2 = *(const float4*)(X + (size_t)n2*HH + c);
        float4 v3 = *(const float4*)(X + (size_t)n3*HH + c);
        acc.x += v0.x + v1.x + v2.x + v3.x;
        acc.y += v0.y + v1.y + v2.y + v3.y;
        acc.z += v0.z + v1.z + v2.z + v3.z;
        acc.w += v0.w + v1.w + v2.w + v3.w;
    }
    for (; j < end; j++){
        int nb = adj[j];
        float4 v = *(const float4*)(X + (size_t)nb*HH + c);
        acc.x += v.x; acc.y += v.y; acc.z += v.z; acc.w += v.w;
    }
    int cnt = end - beg;
    float inv = 1.f / (float)(cnt > 1 ? cnt : 1);
    size_t base = (size_t)w*Kt + coloff + c;
    split_store4(acc.x*inv, acc.y*inv, acc.z*inv, acc.w*inv, oh + base, ol + base);
}

__device__ __forceinline__ void agg_gcn_body(const float* __restrict__ X, const int* __restrict__ adj,
                                             const int* __restrict__ off, const float* __restrict__ dinv,
                                             int n, __nv_bfloat16* __restrict__ oh, __nv_bfloat16* __restrict__ ol,
                                             int Kt, int coloff, int lb){
    int w = (lb*256 + (int)threadIdx.x) >> 5;
    int lane = threadIdx.x & 31;
    if (w >= n) return;
    int beg = off[w], end = off[w+1];
    int c = lane * 4;
    float wd = dinv[w];
    float4 xx = *(const float4*)(X + (size_t)w*HH + c);
    float ws = wd * wd;
    float4 acc = make_float4(ws*xx.x, ws*xx.y, ws*xx.z, ws*xx.w);
    int j = beg;
    for (; j + 4 <= end; j += 4){
        int n0 = adj[j], n1 = adj[j+1], n2 = adj[j+2], n3 = adj[j+3];
        float w0 = wd * dinv[n0], w1 = wd * dinv[n1], w2 = wd * dinv[n2], w3 = wd * dinv[n3];
        float4 v0 = *(const float4*)(X + (size_t)n0*HH + c);
        float4 v1 = *(const float4*)(X + (size_t)n1*HH + c);
        float4 v2 = *(const float4*)(X + (size_t)n2*HH + c);
        float4 v3 = *(const float4*)(X + (size_t)n3*HH + c);
        acc.x += w0*v0.x + w1*v1.x + w2*v2.x + w3*v3.x;
        acc.y += w0*v0.y + w1*v1.y + w2*v2.y + w3*v3.y;
        acc.z += w0*v0.z + w1*v1.z + w2*v2.z + w3*v3.z;
        acc.w += w0*v0.w + w1*v1.w + w2*v2.w + w3*v3.w;
    }
    for (; j < end; j++){
        int nb = adj[j];
        float wn = wd * dinv[nb];
        float4 v = *(const float4*)(X + (size_t)nb*HH + c);
        acc.x += wn*v.x; acc.y += wn*v.y; acc.z += wn*v.z; acc.w += wn*v.w;
    }
    size_t base = (size_t)w*Kt + coloff + c;
    split_store4(acc.x, acc.y, acc.z, acc.w, oh + base, ol + base);
}

__device__ __forceinline__ void root_body(const float* __restrict__ X,
                                          __nv_bfloat16* __restrict__ oh, __nv_bfloat16* __restrict__ ol,
                                          int n, int Kt, int coloff, int lb){
    int idx = lb*256 + (int)threadIdx.x;
    if (idx >= n*32) return;
    int w = idx >> 5, c4 = (idx & 31) * 4;
    float4 v = *(const float4*)(X + (size_t)w*HH + c4);
    size_t base = (size_t)w*Kt + coloff + c4;
    split_store4(v.x, v.y, v.z, v.w, oh + base, ol + base);
}

// ---------------- one fused per-layer aggregation launch (9 segments) ----------------
struct AggArgs {
    const float *xs, *xm, *xr;
    const int *adj0,*off0,*adj2,*off2,*adj4,*off4,*adj5,*off5,*adj1,*off1,*adj3,*off3;
    const float *dinvF,*dinvR;
    __nv_bfloat16 *Amh,*Aml,*Ash,*Asl,*Arh,*Arl;
};
#define AB_M  CDIV(NMm,8)        // 12500 (warp-per-node, 8 nodes/block)
#define AB_RM CDIV(NMm*32,256)   // 12500
#define AB_S  CDIV(NSs,8)        // 625
#define AB_RS CDIV(NSs*32,256)   // 625
#define AB_R  CDIV(NRr,8)        // 250
#define AB_RR CDIV(NRr*32,256)   // 250
#define AS0 AB_M
#define AS1 (AS0 + AB_M)
#define AS2 (AS1 + AB_M)
#define AS3 (AS2 + AB_M)
#define AS4 (AS3 + AB_RM)
#define AS5 (AS4 + AB_S)
#define AS6 (AS5 + AB_RS)
#define AS7 (AS6 + AB_R)
#define AS8 (AS7 + AB_RR)

__global__ void __launch_bounds__(256)
k_agg_all(AggArgs a){
    int b = blockIdx.x;
    if      (b < AS0) agg_mean_body(a.xs, a.adj0, a.off0, NMm, a.Amh, a.Aml, KTM, 0,   b);
    else if (b < AS1) agg_mean_body(a.xr, a.adj2, a.off2, NMm, a.Amh, a.Aml, KTM, 128, b - AS0);
    else if (b < AS2) agg_gcn_body (a.xm, a.adj4, a.off4, a.dinvF, NMm, a.Amh, a.Aml, KTM, 256, b - AS1);
    else if (b < AS3) agg_gcn_body (a.xm, a.adj5, a.off5, a.dinvR, NMm, a.Amh, a.Aml, KTM, 384, b - AS2);
    else if (b < AS4) root_body    (a.xm, a.Amh, a.Aml, NMm, KTM, 512, b - AS3);
    else if (b < AS5) agg_mean_body(a.xm, a.adj1, a.off1, NSs, a.Ash, a.Asl, KT2, 0,   b - AS4);
    else if (b < AS6) root_body    (a.xs, a.Ash, a.Asl, NSs, KT2, 128, b - AS5);
    else if (b < AS7) agg_mean_body(a.xm, a.adj3, a.off3, NRr, a.Arh, a.Arl, KT2, 0,   b - AS6);
    else if (b < AS8) root_body    (a.xr, a.Arh, a.Arl, NRr, KT2, 128, b - AS7);
}

// ---------------- HMMA GEMM: double-buffered cp.async pipeline (R12/R15-exact) ----------------
#define LDSB 72
#define SM_BUF (128*LDSB)
#define SM_BUF_BYTES (SM_BUF*2)
#define STAGE_BYTES (4*SM_BUF_BYTES)
#define SMEM_MMA_BYTES (2*STAGE_BYTES)

__device__ __forceinline__ uint32_t smem_u32(const void* p){
    uint32_t a;
    asm("{ .reg .u64 t; cvta.to.shared.u64 t, %1; cvt.u32.u64 %0, t; }" : "=r"(a) : "l"(p));
    return a;
}
#define CP_ASYNC16(dst, src, sz) \
    asm volatile("cp.async.cg.shared.global [%0], [%1], 16, %2;" :: "r"(dst), "l"(src), "r"(sz))
#define CP_COMMIT() asm volatile("cp.async.commit_group;" ::: "memory")
#define CP_WAIT1()  asm volatile("cp.async.wait_group 1;" ::: "memory")
#define CP_WAIT0()  asm volatile("cp.async.wait_group 0;" ::: "memory")

__device__ __forceinline__ void mma_bf16(float* c, const uint32_t* a, const uint32_t* b){
    asm volatile(
        "mma.sync.aligned.m16n8k16.row.col.f32.bf16.bf16.f32 "
        "{%0,%1,%2,%3}, {%4,%5,%6,%7}, {%8,%9}, {%0,%1,%2,%3};"
        : "+f"(c[0]), "+f"(c[1]), "+f"(c[2]), "+f"(c[3])
        : "r"(a[0]), "r"(a[1]), "r"(a[2]), "r"(a[3]), "r"(b[0]), "r"(b[1]));
}

__global__ void __launch_bounds__(256)
k_mma(const __nv_bfloat16* __restrict__ Ah, const __nv_bfloat16* __restrict__ Al,
      const __nv_bfloat16* __restrict__ Bh, const __nv_bfloat16* __restrict__ Bl,
      const float* __restrict__ bias, float* __restrict__ Xout, int n, int Ktot)
{
    extern __shared__ char smem[];
    const uint32_t sbase = smem_u32(smem);
    const int tid  = threadIdx.x;
    const int wid  = tid >> 5;
    const int lane = tid & 31;
    const int g    = lane >> 2;
    const int t2   = lane & 3;
    const int warp_m = wid & 1;
    const int warp_n = wid >> 1;
    const int row0 = blockIdx.x * 128;
    const int NC = Ktot >> 6;

    float acc[4][4][4];
    #pragma unroll
    for (int mt = 0; mt < 4; mt++)
        #pragma unroll
        for (int nt = 0; nt < 4; nt++)
            #pragma unroll
            for (int r = 0; r < 4; r++) acc[mt][nt][r] = 0.f;

    auto issue = [&](int cch){
        const int stg = cch & 1;
        const uint32_t stb = sbase + stg*STAGE_BYTES;
        const int kc = cch << 6;
        #pragma unroll
        for (int j = 0; j < 4; j++){
            int idx = tid + j*256;
            int row = idx >> 3, c8 = idx & 7;
            uint32_t soff = (uint32_t)(row*LDSB + c8*8) * 2;
            int gr = row0 + row;
            uint32_t sza = (gr < n) ? 16u : 0u;
            CP_ASYNC16(stb + 0*SM_BUF_BYTES + soff, (const char*)(Ah + (size_t)gr*Ktot + kc + c8*8), sza);
            CP_ASYNC16(stb + 1*SM_BUF_BYTES + soff, (const char*)(Al + (size_t)gr*Ktot + kc + c8*8), sza);
            CP_ASYNC16(stb + 2*SM_BUF_BYTES + soff, (const char*)(Bh + (size_t)row*Ktot + kc + c8*8), 16u);
            CP_ASYNC16(stb + 3*SM_BUF_BYTES + soff, (const char*)(Bl + (size_t)row*Ktot + kc + c8*8), 16u);
        }
    };

    issue(0); CP_COMMIT();
    if (NC > 1){ issue(1); CP_COMMIT(); }

    for (int cch = 0; cch < NC; cch++){
        if (cch + 1 < NC) CP_WAIT1(); else CP_WAIT0();
        __syncthreads();

        const int stg = cch & 1;
        const __nv_bfloat16* sAh = (const __nv_bfloat16*)(smem + stg*STAGE_BYTES);
        const __nv_bfloat16* sAl = sAh + SM_BUF;
        const __nv_bfloat16* sBh = sAh + 2*SM_BUF;
        const __nv_bfloat16* sBl = sAh + 3*SM_BUF;

        #pragma unroll
        for (int ks = 0; ks < 4; ks++){
            const int k0 = ks * 16;
            uint32_t afh[4][4], afl[4][4], bfh[4][2], bfl[4][2];
            #pragma unroll
            for (int mt = 0; mt < 4; mt++){
                int rbase = warp_m*64 + mt*16;
                #pragma unroll
                for (int r = 0; r < 4; r++){
                    int row = rbase + g + (r & 1)*8;
                    int col = k0 + t2*2 + (r >> 1)*8;
                    afh[mt][r] = *(const uint32_t*)(sAh + row*LDSB + col);
                    afl[mt][r] = *(const uint32_t*)(sAl + row*LDSB + col);
                }
            }
            #pragma unroll
            for (int nt = 0; nt < 4; nt++){
                int nrow = warp_n*32 + nt*8 + g;
                #pragma unroll
                for (int r = 0; r < 2; r++){
                    int col = k0 + t2*2 + r*8;
                    bfh[nt][r] = *(const uint32_t*)(sBh + nrow*LDSB + col);
                    bfl[nt][r] = *(const uint32_t*)(sBl + nrow*LDSB + col);
                }
            }
            #pragma unroll
            for (int mt = 0; mt < 4; mt++)
                #pragma unroll
                for (int nt = 0; nt < 4; nt++){
                    mma_bf16(acc[mt][nt], afh[mt], bfh[nt]);
                    mma_bf16(acc[mt][nt], afh[mt], bfl[nt]);
                    mma_bf16(acc[mt][nt], afl[mt], bfh[nt]);
                }
        }
        __syncthreads();
        if (cch + 2 < NC){ issue(cch + 2); CP_COMMIT(); }
    }

    #pragma unroll
    for (int mt = 0; mt < 4; mt++){
        #pragma unroll
        for (int nt = 0; nt < 4; nt++){
            int col = warp_n*32 + nt*8 + t2*2;
            float b0 = bias[col], b1 = bias[col+1];
            int r0 = row0 + warp_m*64 + mt*16 + g;
            if (r0 < n){
                float2 o;
                o.x = fmaxf(acc[mt][nt][0] + b0, 0.f);
                o.y = fmaxf(acc[mt][nt][1] + b1, 0.f);
                *(float2*)(Xout + (size_t)r0*HH + col) = o;
            }
            int r1 = r0 + 8;
            if (r1 < n){
                float2 o;
                o.x = fmaxf(acc[mt][nt][2] + b0, 0.f);
                o.y = fmaxf(acc[mt][nt][3] + b1, 0.f);
                *(float2*)(Xout + (size_t)r1*HH + col) = o;
            }
        }
    }
}

// ---------------- fused readout ----------------
__global__ void k_pred(const float* __restrict__ XS, const float* __restrict__ XM,
                       const float* __restrict__ XR,
                       const int* __restrict__ ls, const int* __restrict__ lm,
                       const int* __restrict__ lr, float* __restrict__ out){
    int w = (blockIdx.x*blockDim.x + threadIdx.x) >> 5;
    int lane = threadIdx.x & 31;
    if (w >= LL) return;
    const float* m = XM + (size_t)lm[w]*HH;
    const float* s = XS + (size_t)ls[w]*HH;
    const float* r = XR + (size_t)lr[w]*HH;
    float4 vm = *(const float4*)(m + lane*4);
    float4 vs = *(const float4*)(s + lane*4);
    float4 vr = *(const float4*)(r + lane*4);
    float ds = vs.x*vm.x + vs.y*vm.y + vs.z*vm.z + vs.w*vm.w;
    float dr = vr.x*vm.x + vr.y*vm.y + vr.z*vm.z + vr.w*vm.w;
    #pragma unroll
    for (int d = 16; d; d >>= 1){
        ds += __shfl_xor_sync(0xffffffffu, ds, d);
        dr += __shfl_xor_sync(0xffffffffu, dr, d);
    }
    if (lane == 0){ out[w] = ds; out[LL + w] = dr; }
}

// ---------------- host ----------------
static inline void* symaddr(const void* sym){
    void* p = nullptr;
    cudaGetSymbolAddress(&p, sym);
    return p;
}

extern "C" void kernel_launch(void* const* d_in, const int* in_sizes, int n_in,
                              void* d_out, int out_size){
    const float* emb_s  = (const float*)d_in[0];
    const float* emb_m  = (const float*)d_in[1];
    const float* emb_r  = (const float*)d_in[2];
    const float* sageWl = (const float*)d_in[3];
    const float* sageBl = (const float*)d_in[4];
    const float* sageWr = (const float*)d_in[5];
    const float* gcnW   = (const float*)d_in[6];
    const float* gcnB   = (const float*)d_in[7];
    const int* src_sm   = (const int*)d_in[8];
    const int* dst_sm   = (const int*)d_in[9];
    const int* src_rm   = (const int*)d_in[10];
    const int* dst_rm   = (const int*)d_in[11];
    const int* src_sim  = (const int*)d_in[12];
    const int* dst_sim  = (const int*)d_in[13];
    const int* lbl_s    = (const int*)d_in[14];
    const int* lbl_m    = (const int*)d_in[15];
    const int* lbl_r    = (const int*)d_in[16];
    float* out = (float*)d_out;

    cudaFuncSetAttribute(k_mma, cudaFuncAttributeMaxDynamicSharedMemorySize, SMEM_MMA_BYTES);

    float* XS = (float*)symaddr(g_XS);
    float* XM = (float*)symaddr(g_XM);
    float* XR = (float*)symaddr(g_XR);
    __nv_bfloat16* Amh = (__nv_bfloat16*)symaddr(g_Amh);
    __nv_bfloat16* Aml = (__nv_bfloat16*)symaddr(g_Aml);
    __nv_bfloat16* Ash = (__nv_bfloat16*)symaddr(g_Ash);
    __nv_bfloat16* Asl = (__nv_bfloat16*)symaddr(g_Asl);
    __nv_bfloat16* Arh = (__nv_bfloat16*)symaddr(g_Arh);
    __nv_bfloat16* Arl = (__nv_bfloat16*)symaddr(g_Arl);
    __nv_bfloat16* Bmh = (__nv_bfloat16*)symaddr(g_Bmh);
    __nv_bfloat16* Bml = (__nv_bfloat16*)symaddr(g_Bml);
    __nv_bfloat16* Bsh = (__nv_bfloat16*)symaddr(g_Bsh);
    __nv_bfloat16* Bsl = (__nv_bfloat16*)symaddr(g_Bsl);
    __nv_bfloat16* Brh = (__nv_bfloat16*)symaddr(g_Brh);
    __nv_bfloat16* Brl = (__nv_bfloat16*)symaddr(g_Brl);
    float* biasM = (float*)symaddr(g_biasM);
    int* adj0 = (int*)symaddr(g_adj0);
    int* adj1 = (int*)symaddr(g_adj1);
    int* adj2 = (int*)symaddr(g_adj2);
    int* adj3 = (int*)symaddr(g_adj3);
    int* adj4 = (int*)symaddr(g_adj4);
    int* adj5 = (int*)symaddr(g_adj5);
    int* off0 = (int*)symaddr(g_off0);
    int* off1 = (int*)symaddr(g_off1);
    int* off2 = (int*)symaddr(g_off2);
    int* off3 = (int*)symaddr(g_off3);
    int* off4 = (int*)symaddr(g_off4);
    int* off5 = (int*)symaddr(g_off5);
    int* cnt6  = (int*)symaddr(g_cnt6);
    int* incl6 = (int*)symaddr(g_incl6);
    int* cur6  = (int*)symaddr(g_cur6);
    int* bsum6 = (int*)symaddr(g_bsums6);
    float* dinvF = (float*)symaddr(g_dinvF);
    float* dinvR = (float*)symaddr(g_dinvR);

    // ---- batched CSR build ----
    CsrArgs ca;
    ca.k0 = dst_sm;  ca.v0 = src_sm;
    ca.k1 = src_sm;  ca.v1 = dst_sm;
    ca.k2 = dst_rm;  ca.v2 = src_rm;
    ca.k3 = src_rm;  ca.v3 = dst_rm;
    ca.k4 = dst_sim; ca.v4 = src_sim;
    ca.k5 = src_sim; ca.v5 = dst_sim;
    OffPtrs op = { off0, off1, off2, off3, off4, off5 };
    AdjPtrs ap = { adj0, adj1, adj2, adj3, adj4, adj5 };

    k_zero_i<<<CDIV(CNT_TOT,256),256>>>(cnt6, CNT_TOT);
    k_count_all<<<EDGE_BLKS,256>>>(ca, cnt6);
    k_scan1_all<<<SCAN_BLKS,1024>>>(cnt6, incl6, bsum6);
    k_scan2_all<<<6,1024>>>(bsum6);
    k_scan3_all<<<SCAN_BLKS,1024>>>(incl6, bsum6, cnt6, op, cur6);
    k_fill_all<<<EDGE_BLKS,256>>>(ca, ap, cur6);
    k_dinv2<<<CDIV(NMm,256),256>>>(off4, off5, dinvF, dinvR);

    const int HW = HH*HH;

    for (int l = 0; l < 2; l++){
        const float* xs = l ? XS : emb_s;
        const float* xm = l ? XM : emb_m;
        const float* xr = l ? XR : emb_r;
        float* XSo = XS + (size_t)l*NSs*HH;
        float* XMo = XM + (size_t)l*NMm*HH;
        float* XRo = XR + (size_t)l*NRr*HH;

        WArgs wa;
        wa.Wl0 = sageWl + (size_t)(l*4+0)*HW;
        wa.Wl1 = sageWl + (size_t)(l*4+1)*HW;
        wa.Wl2 = sageWl + (size_t)(l*4+2)*HW;
        wa.Wl3 = sageWl + (size_t)(l*4+3)*HW;
        wa.bl0 = sageBl + (size_t)(l*4+0)*HH;
        wa.bl2 = sageBl + (size_t)(l*4+2)*HH;
        wa.Wr0 = sageWr + (size_t)(l*4+0)*HW;
        wa.Wr1 = sageWr + (size_t)(l*4+1)*HW;
        wa.Wr2 = sageWr + (size_t)(l*4+2)*HW;
        wa.Wr3 = sageWr + (size_t)(l*4+3)*HW;
        wa.gW0 = gcnW + (size_t)(l*2+0)*HW;
        wa.gW1 = gcnW + (size_t)(l*2+1)*HW;
        wa.gb0 = gcnB + (size_t)(l*2+0)*HH;
        wa.gb1 = gcnB + (size_t)(l*2+1)*HH;
        wa.Bmh = Bmh; wa.Bml = Bml; wa.Bsh = Bsh; wa.Bsl = Bsl;
        wa.Brh = Brh; wa.Brl = Brl; wa.biasM = biasM;
        k_buildW<<<WB_TOT,256>>>(wa);

        AggArgs aa;
        aa.xs = xs; aa.xm = xm; aa.xr = xr;
        aa.adj0 = adj0; aa.off0 = off0;
        aa.adj2 = adj2; aa.off2 = off2;
        aa.adj4 = adj4; aa.off4 = off4;
        aa.adj5 = adj5; aa.off5 = off5;
        aa.adj1 = adj1; aa.off1 = off1;
        aa.adj3 = adj3; aa.off3 = off3;
        aa.dinvF = dinvF; aa.dinvR = dinvR;
        aa.Amh = Amh; aa.Aml = Aml; aa.Ash = Ash; aa.Asl = Asl; aa.Arh = Arh; aa.Arl = Arl;
        k_agg_all<<<AS8,256>>>(aa);

        const float* bl1 = sageBl + (size_t)(l*4+1)*HH;
        const float* bl3 = sageBl + (size_t)(l*4+3)*HH;
        // pipelined HMMA GEMMs (bias+relu fused)
        k_mma<<<CDIV(NMm,128),256,SMEM_MMA_BYTES>>>(Amh, Aml, Bmh, Bml, biasM, XMo, NMm, KTM);
        k_mma<<<CDIV(NSs,128),256,SMEM_MMA_BYTES>>>(Ash, Asl, Bsh, Bsl, bl1, XSo, NSs, KT2);
        k_mma<<<CDIV(NRr,128),256,SMEM_MMA_BYTES>>>(Arh, Arl, Brh, Brl, bl3, XRo, NRr, KT2);
    }

    const float* XSf = XS + (size_t)1*NSs*HH;
    const float* XMf = XM + (size_t)1*NMm*HH;
    const float* XRf = XR + (size_t)1*NRr*HH;
    k_pred<<<CDIV(LL,8),256>>>(XSf, XMf, XRf, lbl_s, lbl_m, lbl_r, out);

    (void)in_sizes; (void)n_in; (void)out_size;
}

// round 17
// speedup vs baseline: 1.9056x; 1.0346x over previous
#include <cuda_runtime.h>
#include <cuda_bf16.h>
#include <cstdint>

#define NSs   5000
#define NMm   100000
#define NRr   2000
#define HH    128
#define ESM   2000000
#define ERM   1000000
#define ESIM  2000000
#define LL    500000
#define KTM   640
#define KT2   256

#define CDIV(a,b) (((a)+(b)-1)/(b))

// ---------------- device scratch ----------------
static __device__ float g_XS[2][NSs*HH];
static __device__ float g_XM[2][NMm*HH];
static __device__ float g_XR[2][NRr*HH];

static __device__ __nv_bfloat16 g_Amh[(size_t)NMm*KTM];
static __device__ __nv_bfloat16 g_Aml[(size_t)NMm*KTM];
static __device__ __nv_bfloat16 g_Ash[(size_t)NSs*KT2];
static __device__ __nv_bfloat16 g_Asl[(size_t)NSs*KT2];
static __device__ __nv_bfloat16 g_Arh[(size_t)NRr*KT2];
static __device__ __nv_bfloat16 g_Arl[(size_t)NRr*KT2];

static __device__ __nv_bfloat16 g_Bmh[HH*KTM], g_Bml[HH*KTM];
static __device__ __nv_bfloat16 g_Bsh[HH*KT2], g_Bsl[HH*KT2];
static __device__ __nv_bfloat16 g_Brh[HH*KT2], g_Brl[HH*KT2];
static __device__ float g_biasM[HH];

static __device__ int g_adj0[ESM];
static __device__ int g_adj1[ESM];
static __device__ int g_adj2[ERM];
static __device__ int g_adj3[ERM];
static __device__ int g_adj4[ESIM];
static __device__ int g_adj5[ESIM];

static __device__ int g_off0[NMm+1];
static __device__ int g_off1[NSs+1];
static __device__ int g_off2[NMm+1];
static __device__ int g_off3[NRr+1];
static __device__ int g_off4[NMm+1];
static __device__ int g_off5[NMm+1];

#define CNT_O0 0
#define CNT_O1 (NMm)
#define CNT_O2 (NMm+NSs)
#define CNT_O3 (2*NMm+NSs)
#define CNT_O4 (2*NMm+NSs+NRr)
#define CNT_O5 (3*NMm+NSs+NRr)
#define CNT_TOT (4*NMm+NSs+NRr)
static __device__ int g_cnt6[CNT_TOT];
static __device__ int g_incl6[CNT_TOT];
static __device__ int g_cur6[CNT_TOT];
static __device__ int g_bsums6[6*1024];

static __device__ float g_dinvF[NMm];
static __device__ float g_dinvR[NMm];

// ---------------- bf16 hi/lo split helper ----------------
__device__ __forceinline__ void split_store4(float a, float b, float c, float d,
                                             __nv_bfloat16* oh, __nv_bfloat16* ol){
    __nv_bfloat16 ha = __float2bfloat16(a), hb = __float2bfloat16(b),
                  hc = __float2bfloat16(c), hd = __float2bfloat16(d);
    __nv_bfloat16 la = __float2bfloat16(a - __bfloat162float(ha));
    __nv_bfloat16 lb = __float2bfloat16(b - __bfloat162float(hb));
    __nv_bfloat16 lc = __float2bfloat16(c - __bfloat162float(hc));
    __nv_bfloat16 ld = __float2bfloat16(d - __bfloat162float(hd));
    ushort4 H; H.x = __bfloat16_as_ushort(ha); H.y = __bfloat16_as_ushort(hb);
               H.z = __bfloat16_as_ushort(hc); H.w = __bfloat16_as_ushort(hd);
    ushort4 L; L.x = __bfloat16_as_ushort(la); L.y = __bfloat16_as_ushort(lb);
               L.z = __bfloat16_as_ushort(lc); L.w = __bfloat16_as_ushort(ld);
    *(ushort4*)oh = H;
    *(ushort4*)ol = L;
}

// ================= batched CSR build (R11-proven) =================
#define NB_E2M CDIV(ESM,256)
#define NB_E1M CDIV(ERM,256)
#define EDGE_BLKS (4*NB_E2M + 2*NB_E1M)
#define SB_NM CDIV(NMm,1024)
#define SB_NS CDIV(NSs,1024)
#define SB_NR CDIV(NRr,1024)
#define SCAN_BLKS (4*SB_NM + SB_NS + SB_NR)

struct CsrArgs {
    const int *k0,*k1,*k2,*k3,*k4,*k5;
    const int *v0,*v1,*v2,*v3,*v4,*v5;
};
struct OffPtrs  { int *o0,*o1,*o2,*o3,*o4,*o5; };
struct AdjPtrs  { int *a0,*a1,*a2,*a3,*a4,*a5; };

__device__ __forceinline__ void seg6_edges(int b, int& seg, int& lb){
    if      (b < NB_E2M)                      { seg=0; lb=b; }
    else if (b < 2*NB_E2M)                    { seg=1; lb=b-NB_E2M; }
    else if (b < 2*NB_E2M+NB_E1M)             { seg=2; lb=b-2*NB_E2M; }
    else if (b < 2*NB_E2M+2*NB_E1M)           { seg=3; lb=b-2*NB_E2M-NB_E1M; }
    else if (b < 3*NB_E2M+2*NB_E1M)           { seg=4; lb=b-2*NB_E2M-2*NB_E1M; }
    else                                      { seg=5; lb=b-3*NB_E2M-2*NB_E1M; }
}
__device__ __forceinline__ void seg6_scan(int b, int& seg, int& lb){
    if      (b < SB_NM)                      { seg=0; lb=b; }
    else if (b < SB_NM+SB_NS)                { seg=1; lb=b-SB_NM; }
    else if (b < 2*SB_NM+SB_NS)              { seg=2; lb=b-SB_NM-SB_NS; }
    else if (b < 2*SB_NM+SB_NS+SB_NR)        { seg=3; lb=b-2*SB_NM-SB_NS; }
    else if (b < 3*SB_NM+SB_NS+SB_NR)        { seg=4; lb=b-2*SB_NM-SB_NS-SB_NR; }
    else                                     { seg=5; lb=b-3*SB_NM-SB_NS-SB_NR; }
}
__device__ __forceinline__ void seg_scan_params(int seg, int& n, int& co){
    switch(seg){
        case 0: n=NMm; co=CNT_O0; break;
        case 1: n=NSs; co=CNT_O1; break;
        case 2: n=NMm; co=CNT_O2; break;
        case 3: n=NRr; co=CNT_O3; break;
        case 4: n=NMm; co=CNT_O4; break;
        default:n=NMm; co=CNT_O5; break;
    }
}

__global__ void k_zero_i(int* p, int n){
    int i = blockIdx.x*blockDim.x + threadIdx.x;
    if (i < n) p[i] = 0;
}
__global__ void k_count_all(CsrArgs a, int* __restrict__ cnt){
    int seg, lb; seg6_edges(blockIdx.x, seg, lb);
    int i = lb*256 + threadIdx.x;
    const int* key; int e, co;
    switch(seg){
        case 0: key=a.k0; e=ESM;  co=CNT_O0; break;
        case 1: key=a.k1; e=ESM;  co=CNT_O1; break;
        case 2: key=a.k2; e=ERM;  co=CNT_O2; break;
        case 3: key=a.k3; e=ERM;  co=CNT_O3; break;
        case 4: key=a.k4; e=ESIM; co=CNT_O4; break;
        default:key=a.k5; e=ESIM; co=CNT_O5; break;
    }
    if (i < e) atomicAdd(&cnt[co + key[i]], 1);
}
__global__ void k_scan1_all(const int* __restrict__ cnt, int* __restrict__ incl,
                            int* __restrict__ bsums){
    __shared__ int sh[1024];
    int seg, lb; seg6_scan(blockIdx.x, seg, lb);
    int n, co; seg_scan_params(seg, n, co);
    int i = lb*1024 + threadIdx.x;
    sh[threadIdx.x] = (i < n) ? cnt[co + i] : 0;
    __syncthreads();
    for (int d = 1; d < 1024; d <<= 1){
        int t = (threadIdx.x >= d) ? sh[threadIdx.x - d] : 0;
        __syncthreads();
        sh[threadIdx.x] += t;
        __syncthreads();
    }
    if (i < n) incl[co + i] = sh[threadIdx.x];
    if (threadIdx.x == 1023) bsums[seg*1024 + lb] = sh[1023];
}
__global__ void k_scan2_all(int* bsums){
    __shared__ int sh[1024];
    int seg = blockIdx.x;
    int n, co; seg_scan_params(seg, n, co);
    int nb = CDIV(n, 1024);
    sh[threadIdx.x] = (threadIdx.x < nb) ? bsums[seg*1024 + threadIdx.x] : 0;
    __syncthreads();
    for (int d = 1; d < 1024; d <<= 1){
        int t = (threadIdx.x >= d) ? sh[threadIdx.x - d] : 0;
        __syncthreads();
        sh[threadIdx.x] += t;
        __syncthreads();
    }
    if (threadIdx.x < nb) bsums[seg*1024 + threadIdx.x] = sh[threadIdx.x];
}
__global__ void k_scan3_all(const int* __restrict__ incl, const int* __restrict__ bsums,
                            const int* __restrict__ cnt, OffPtrs op, int* __restrict__ cur){
    int seg, lb; seg6_scan(blockIdx.x, seg, lb);
    int n, co; seg_scan_params(seg, n, co);
    int* off;
    switch(seg){ case 0: off=op.o0; break; case 1: off=op.o1; break; case 2: off=op.o2; break;
                 case 3: off=op.o3; break; case 4: off=op.o4; break; default: off=op.o5; break; }
    int i = lb*1024 + threadIdx.x;
    if (i < n){
        int add = lb ? bsums[seg*1024 + lb - 1] : 0;
        int v = incl[co + i] + add;
        off[i+1] = v;
        if (i == 0) off[0] = 0;
        cur[co + i] = v - cnt[co + i];
    }
}
__global__ void k_fill_all(CsrArgs a, AdjPtrs ap, int* __restrict__ cur){
    int seg, lb; seg6_edges(blockIdx.x, seg, lb);
    int i = lb*256 + threadIdx.x;
    const int *key, *val; int e, co; int* adj;
    switch(seg){
        case 0: key=a.k0; val=a.v0; e=ESM;  co=CNT_O0; adj=ap.a0; break;
        case 1: key=a.k1; val=a.v1; e=ESM;  co=CNT_O1; adj=ap.a1; break;
        case 2: key=a.k2; val=a.v2; e=ERM;  co=CNT_O2; adj=ap.a2; break;
        case 3: key=a.k3; val=a.v3; e=ERM;  co=CNT_O3; adj=ap.a3; break;
        case 4: key=a.k4; val=a.v4; e=ESIM; co=CNT_O4; adj=ap.a4; break;
        default:key=a.k5; val=a.v5; e=ESIM; co=CNT_O5; adj=ap.a5; break;
    }
    if (i < e){
        int p = atomicAdd(&cur[co + key[i]], 1);
        adj[p] = val[i];
    }
}
__global__ void k_dinv2(const int* __restrict__ off4, const int* __restrict__ off5,
                        float* __restrict__ dF, float* __restrict__ dR){
    int i = blockIdx.x*blockDim.x + threadIdx.x;
    if (i < NMm){
        dF[i] = rsqrtf((float)(off4[i+1] - off4[i] + 1));
        dR[i] = rsqrtf((float)(off5[i+1] - off5[i] + 1));
    }
}

// ---------------- aggregation bodies (R15-exact instruction streams) ----------------
__device__ __forceinline__ void agg_mean_body(const float* __restrict__ X, const int* __restrict__ adj,
                                              const int* __restrict__ off, int n,
                                              __nv_bfloat16* __restrict__ oh, __nv_bfloat16* __restrict__ ol,
                                              int Kt, int coloff, int lb){
    int w = (lb*256 + (int)threadIdx.x) >> 5;
    int lane = threadIdx.x & 31;
    if (w >= n) return;
    int beg = off[w], end = off[w+1];
    int c = lane * 4;
    float4 acc = make_float4(0.f, 0.f, 0.f, 0.f);
    int j = beg;
    for (; j + 4 <= end; j += 4){
        int n0 = adj[j], n1 = adj[j+1], n2 = adj[j+2], n3 = adj[j+3];
        float4 v0 = *(const float4*)(X + (size_t)n0*HH + c);
        float4 v1 = *(const float4*)(X + (size_t)n1*HH + c);
        float4 v2 = *(const float4*)(X + (size_t)n2*HH + c);
        float4 v3 = *(const float4*)(X + (size_t)n3*HH + c);
        acc.x += v0.x + v1.x + v2.x + v3.x;
        acc.y += v0.y + v1.y + v2.y + v3.y;
        acc.z += v0.z + v1.z + v2.z + v3.z;
        acc.w += v0.w + v1.w + v2.w + v3.w;
    }
    for (; j < end; j++){
        int nb = adj[j];
        float4 v = *(const float4*)(X + (size_t)nb*HH + c);
        acc.x += v.x; acc.y += v.y; acc.z += v.z; acc.w += v.w;
    }
    int cnt = end - beg;
    float inv = 1.f / (float)(cnt > 1 ? cnt : 1);
    size_t base = (size_t)w*Kt + coloff + c;
    split_store4(acc.x*inv, acc.y*inv, acc.z*inv, acc.w*inv, oh + base, ol + base);
}

__device__ __forceinline__ void agg_gcn_body(const float* __restrict__ X, const int* __restrict__ adj,
                                             const int* __restrict__ off, const float* __restrict__ dinv,
                                             int n, __nv_bfloat16* __restrict__ oh, __nv_bfloat16* __restrict__ ol,
                                             int Kt, int coloff, int lb){
    int w = (lb*256 + (int)threadIdx.x) >> 5;
    int lane = threadIdx.x & 31;
    if (w >= n) return;
    int beg = off[w], end = off[w+1];
    int c = lane * 4;
    float wd = dinv[w];
    float4 xx = *(const float4*)(X + (size_t)w*HH + c);
    float ws = wd * wd;
    float4 acc = make_float4(ws*xx.x, ws*xx.y, ws*xx.z, ws*xx.w);
    int j = beg;
    for (; j + 4 <= end; j += 4){
        int n0 = adj[j], n1 = adj[j+1], n2 = adj[j+2], n3 = adj[j+3];
        float w0 = wd * dinv[n0], w1 = wd * dinv[n1], w2 = wd * dinv[n2], w3 = wd * dinv[n3];
        float4 v0 = *(const float4*)(X + (size_t)n0*HH + c);
        float4 v1 = *(const float4*)(X + (size_t)n1*HH + c);
        float4 v2 = *(const float4*)(X + (size_t)n2*HH + c);
        float4 v3 = *(const float4*)(X + (size_t)n3*HH + c);
        acc.x += w0*v0.x + w1*v1.x + w2*v2.x + w3*v3.x;
        acc.y += w0*v0.y + w1*v1.y + w2*v2.y + w3*v3.y;
        acc.z += w0*v0.z + w1*v1.z + w2*v2.z + w3*v3.z;
        acc.w += w0*v0.w + w1*v1.w + w2*v2.w + w3*v3.w;
    }
    for (; j < end; j++){
        int nb = adj[j];
        float wn = wd * dinv[nb];
        float4 v = *(const float4*)(X + (size_t)nb*HH + c);
        acc.x += wn*v.x; acc.y += wn*v.y; acc.z += wn*v.z; acc.w += wn*v.w;
    }
    size_t base = (size_t)w*Kt + coloff + c;
    split_store4(acc.x, acc.y, acc.z, acc.w, oh + base, ol + base);
}

__device__ __forceinline__ void root_body(const float* __restrict__ X,
                                          __nv_bfloat16* __restrict__ oh, __nv_bfloat16* __restrict__ ol,
                                          int n, int Kt, int coloff, int lb){
    int idx = lb*256 + (int)threadIdx.x;
    if (idx >= n*32) return;
    int w = idx >> 5, c4 = (idx & 31) * 4;
    float4 v = *(const float4*)(X + (size_t)w*HH + c4);
    size_t base = (size_t)w*Kt + coloff + c4;
    split_store4(v.x, v.y, v.z, v.w, oh + base, ol + base);
}

// ---------------- one fused per-layer prep launch (9 agg + 3 weight segments) ----------------
struct AggArgs {
    const float *xs, *xm, *xr;
    const int *adj0,*off0,*adj2,*off2,*adj4,*off4,*adj5,*off5,*adj1,*off1,*adj3,*off3;
    const float *dinvF,*dinvR;
    __nv_bfloat16 *Amh,*Aml,*Ash,*Asl,*Arh,*Arl;
};
struct WArgs {
    const float *Wl0,*Wl1,*Wl2,*Wl3,*bl0,*bl2,*Wr0,*Wr1,*Wr2,*Wr3,*gW0,*gW1,*gb0,*gb1;
    __nv_bfloat16 *Bmh,*Bml,*Bsh,*Bsl,*Brh,*Brl;
    float* biasM;
};
#define AB_M  CDIV(NMm,8)
#define AB_RM CDIV(NMm*32,256)
#define AB_S  CDIV(NSs,8)
#define AB_RS CDIV(NSs*32,256)
#define AB_R  CDIV(NRr,8)
#define AB_RR CDIV(NRr*32,256)
#define WB_M  CDIV(HH*KTM,256)
#define WB_2  CDIV(HH*KT2,256)
#define AS0 AB_M
#define AS1 (AS0 + AB_M)
#define AS2 (AS1 + AB_M)
#define AS3 (AS2 + AB_M)
#define AS4 (AS3 + AB_RM)
#define AS5 (AS4 + AB_S)
#define AS6 (AS5 + AB_RS)
#define AS7 (AS6 + AB_R)
#define AS8 (AS7 + AB_RR)
#define AS9 (AS8 + WB_M)
#define AS10 (AS9 + 2*WB_2)
#define AS11 (AS10 + 1)

__global__ void __launch_bounds__(256)
k_prep_all(AggArgs a, WArgs w){
    int b = blockIdx.x;
    if      (b < AS0) agg_mean_body(a.xs, a.adj0, a.off0, NMm, a.Amh, a.Aml, KTM, 0,   b);
    else if (b < AS1) agg_mean_body(a.xr, a.adj2, a.off2, NMm, a.Amh, a.Aml, KTM, 128, b - AS0);
    else if (b < AS2) agg_gcn_body (a.xm, a.adj4, a.off4, a.dinvF, NMm, a.Amh, a.Aml, KTM, 256, b - AS1);
    else if (b < AS3) agg_gcn_body (a.xm, a.adj5, a.off5, a.dinvR, NMm, a.Amh, a.Aml, KTM, 384, b - AS2);
    else if (b < AS4) root_body    (a.xm, a.Amh, a.Aml, NMm, KTM, 512, b - AS3);
    else if (b < AS5) agg_mean_body(a.xm, a.adj1, a.off1, NSs, a.Ash, a.Asl, KT2, 0,   b - AS4);
    else if (b < AS6) root_body    (a.xs, a.Ash, a.Asl, NSs, KT2, 128, b - AS5);
    else if (b < AS7) agg_mean_body(a.xm, a.adj3, a.off3, NRr, a.Arh, a.Arl, KT2, 0,   b - AS6);
    else if (b < AS8) root_body    (a.xr, a.Arh, a.Arl, NRr, KT2, 128, b - AS7);
    else if (b < AS9){
        int i = (b - AS8)*256 + threadIdx.x;
        int n = i / KTM, k = i % KTM;
        int sl = k >> 7, kk = k & 127;
        float v;
        if      (sl == 0) v = w.Wl0[kk*HH + n];
        else if (sl == 1) v = w.Wl2[kk*HH + n];
        else if (sl == 2) v = w.gW0[kk*HH + n];
        else if (sl == 3) v = w.gW1[kk*HH + n];
        else              v = w.Wr0[kk*HH + n] + w.Wr2[kk*HH + n];
        __nv_bfloat16 h = __float2bfloat16(v);
        w.Bmh[i] = h;
        w.Bml[i] = __float2bfloat16(v - __bfloat162float(h));
    } else if (b < AS10){
        int w2 = b - AS9;
        int which = w2 / WB_2;
        int i = (w2 % WB_2)*256 + threadIdx.x;
        int n = i / KT2, k = i % KT2;
        const float* Wa = which ? w.Wl3 : w.Wl1;
        const float* Wb = which ? w.Wr3 : w.Wr1;
        float v = (k < 128) ? Wa[(k&127)*HH + n] : Wb[(k&127)*HH + n];
        __nv_bfloat16 h = __float2bfloat16(v);
        __nv_bfloat16* oh = which ? w.Brh : w.Bsh;
        __nv_bfloat16* ol = which ? w.Brl : w.Bsl;
        oh[i] = h;
        ol[i] = __float2bfloat16(v - __bfloat162float(h));
    } else {
        int i = threadIdx.x;
        if (i < HH) w.biasM[i] = w.bl0[i] + w.bl2[i] + w.gb0[i] + w.gb1[i];
    }
}

// ---------------- batched HMMA GEMM: 3 segments in one launch ----------------
#define LDSB 72
#define SM_BUF (128*LDSB)
#define SM_BUF_BYTES (SM_BUF*2)
#define STAGE_BYTES (4*SM_BUF_BYTES)
#define SMEM_MMA_BYTES (2*STAGE_BYTES)
#define MB_M CDIV(NMm,128)     // 782
#define MB_S CDIV(NSs,128)     // 40
#define MB_R CDIV(NRr,128)     // 16
#define MB_TOT (MB_M + MB_S + MB_R)

__device__ __forceinline__ uint32_t smem_u32(const void* p){
    uint32_t a;
    asm("{ .reg .u64 t; cvta.to.shared.u64 t, %1; cvt.u32.u64 %0, t; }" : "=r"(a) : "l"(p));
    return a;
}
#define CP_ASYNC16(dst, src, sz) \
    asm volatile("cp.async.cg.shared.global [%0], [%1], 16, %2;" :: "r"(dst), "l"(src), "r"(sz))
#define CP_COMMIT() asm volatile("cp.async.commit_group;" ::: "memory")
#define CP_WAIT1()  asm volatile("cp.async.wait_group 1;" ::: "memory")
#define CP_WAIT0()  asm volatile("cp.async.wait_group 0;" ::: "memory")

__device__ __forceinline__ void mma_bf16(float* c, const uint32_t* a, const uint32_t* b){
    asm volatile(
        "mma.sync.aligned.m16n8k16.row.col.f32.bf16.bf16.f32 "
        "{%0,%1,%2,%3}, {%4,%5,%6,%7}, {%8,%9}, {%0,%1,%2,%3};"
        : "+f"(c[0]), "+f"(c[1]), "+f"(c[2]), "+f"(c[3])
        : "r"(a[0]), "r"(a[1]), "r"(a[2]), "r"(a[3]), "r"(b[0]), "r"(b[1]));
}

__global__ void __launch_bounds__(256)
k_mma3(const __nv_bfloat16* __restrict__ Amh, const __nv_bfloat16* __restrict__ Aml,
       const __nv_bfloat16* __restrict__ Bmh, const __nv_bfloat16* __restrict__ Bml,
       const float* __restrict__ biasM, float* __restrict__ XMo,
       const __nv_bfloat16* __restrict__ Ash, const __nv_bfloat16* __restrict__ Asl,
       const __nv_bfloat16* __restrict__ Bsh, const __nv_bfloat16* __restrict__ Bsl,
       const float* __restrict__ biasS, float* __restrict__ XSo,
       const __nv_bfloat16* __restrict__ Arh, const __nv_bfloat16* __restrict__ Arl,
       const __nv_bfloat16* __restrict__ Brh, const __nv_bfloat16* __restrict__ Brl,
       const float* __restrict__ biasR, float* __restrict__ XRo)
{
    // uniform per-block segment select (flat pointers, no struct copy)
    const __nv_bfloat16 *Ah, *Al, *Bh, *Bl;
    const float* bias;
    float* Xout;
    int n, Ktot, lb;
    {
        int b = blockIdx.x;
        if (b < MB_M){
            Ah = Amh; Al = Aml; Bh = Bmh; Bl = Bml; bias = biasM; Xout = XMo;
            n = NMm; Ktot = KTM; lb = b;
        } else if (b < MB_M + MB_S){
            Ah = Ash; Al = Asl; Bh = Bsh; Bl = Bsl; bias = biasS; Xout = XSo;
            n = NSs; Ktot = KT2; lb = b - MB_M;
        } else {
            Ah = Arh; Al = Arl; Bh = Brh; Bl = Brl; bias = biasR; Xout = XRo;
            n = NRr; Ktot = KT2; lb = b - MB_M - MB_S;
        }
    }

    extern __shared__ char smem[];
    const uint32_t sbase = smem_u32(smem);
    const int tid  = threadIdx.x;
    const int wid  = tid >> 5;
    const int lane = tid & 31;
    const int g    = lane >> 2;
    const int t2   = lane & 3;
    const int warp_m = wid & 1;
    const int warp_n = wid >> 1;
    const int row0 = lb * 128;
    const int NC = Ktot >> 6;

    float acc[4][4][4];
    #pragma unroll
    for (int mt = 0; mt < 4; mt++)
        #pragma unroll
        for (int nt = 0; nt < 4; nt++)
            #pragma unroll
            for (int r = 0; r < 4; r++) acc[mt][nt][r] = 0.f;

    auto issue = [&](int cch){
        const int stg = cch & 1;
        const uint32_t stb = sbase + stg*STAGE_BYTES;
        const int kc = cch << 6;
        #pragma unroll
        for (int j = 0; j < 4; j++){
            int idx = tid + j*256;
            int row = idx >> 3, c8 = idx & 7;
            uint32_t soff = (uint32_t)(row*LDSB + c8*8) * 2;
            int gr = row0 + row;
            uint32_t sza = (gr < n) ? 16u : 0u;
            CP_ASYNC16(stb + 0*SM_BUF_BYTES + soff, (const char*)(Ah + (size_t)gr*Ktot + kc + c8*8), sza);
            CP_ASYNC16(stb + 1*SM_BUF_BYTES + soff, (const char*)(Al + (size_t)gr*Ktot + kc + c8*8), sza);
            CP_ASYNC16(stb + 2*SM_BUF_BYTES + soff, (const char*)(Bh + (size_t)row*Ktot + kc + c8*8), 16u);
            CP_ASYNC16(stb + 3*SM_BUF_BYTES + soff, (const char*)(Bl + (size_t)row*Ktot + kc + c8*8), 16u);
        }
    };

    issue(0); CP_COMMIT();
    if (NC > 1){ issue(1); CP_COMMIT(); }

    for (int cch = 0; cch < NC; cch++){
        if (cch + 1 < NC) CP_WAIT1(); else CP_WAIT0();
        __syncthreads();

        const int stg = cch & 1;
        const __nv_bfloat16* sAh = (const __nv_bfloat16*)(smem + stg*STAGE_BYTES);
        const __nv_bfloat16* sAl = sAh + SM_BUF;
        const __nv_bfloat16* sBh = sAh + 2*SM_BUF;
        const __nv_bfloat16* sBl = sAh + 3*SM_BUF;

        #pragma unroll
        for (int ks = 0; ks < 4; ks++){
            const int k0 = ks * 16;
            uint32_t afh[4][4], afl[4][4], bfh[4][2], bfl[4][2];
            #pragma unroll
            for (int mt = 0; mt < 4; mt++){
                int rbase = warp_m*64 + mt*16;
                #pragma unroll
                for (int r = 0; r < 4; r++){
                    int row = rbase + g + (r & 1)*8;
                    int col = k0 + t2*2 + (r >> 1)*8;
                    afh[mt][r] = *(const uint32_t*)(sAh + row*LDSB + col);
                    afl[mt][r] = *(const uint32_t*)(sAl + row*LDSB + col);
                }
            }
            #pragma unroll
            for (int nt = 0; nt < 4; nt++){
                int nrow = warp_n*32 + nt*8 + g;
                #pragma unroll
                for (int r = 0; r < 2; r++){
                    int col = k0 + t2*2 + r*8;
                    bfh[nt][r] = *(const uint32_t*)(sBh + nrow*LDSB + col);
                    bfl[nt][r] = *(const uint32_t*)(sBl + nrow*LDSB + col);
                }
            }
            #pragma unroll
            for (int mt = 0; mt < 4; mt++)
                #pragma unroll
                for (int nt = 0; nt < 4; nt++){
                    mma_bf16(acc[mt][nt], afh[mt], bfh[nt]);
                    mma_bf16(acc[mt][nt], afh[mt], bfl[nt]);
                    mma_bf16(acc[mt][nt], afl[mt], bfh[nt]);
                }
        }
        __syncthreads();
        if (cch + 2 < NC){ issue(cch + 2); CP_COMMIT(); }
    }

    #pragma unroll
    for (int mt = 0; mt < 4; mt++){
        #pragma unroll
        for (int nt = 0; nt < 4; nt++){
            int col = warp_n*32 + nt*8 + t2*2;
            float b0 = bias[col], b1 = bias[col+1];
            int r0 = row0 + warp_m*64 + mt*16 + g;
            if (r0 < n){
                float2 o;
                o.x = fmaxf(acc[mt][nt][0] + b0, 0.f);
                o.y = fmaxf(acc[mt][nt][1] + b1, 0.f);
                *(float2*)(Xout + (size_t)r0*HH + col) = o;
            }
            int r1 = r0 + 8;
            if (r1 < n){
                float2 o;
                o.x = fmaxf(acc[mt][nt][2] + b0, 0.f);
                o.y = fmaxf(acc[mt][nt][3] + b1, 0.f);
                *(float2*)(Xout + (size_t)r1*HH + col) = o;
            }
        }
    }
}

// ---------------- fused readout ----------------
__global__ void k_pred(const float* __restrict__ XS, const float* __restrict__ XM,
                       const float* __restrict__ XR,
                       const int* __restrict__ ls, const int* __restrict__ lm,
                       const int* __restrict__ lr, float* __restrict__ out){
    int w = (blockIdx.x*blockDim.x + threadIdx.x) >> 5;
    int lane = threadIdx.x & 31;
    if (w >= LL) return;
    const float* m = XM + (size_t)lm[w]*HH;
    const float* s = XS + (size_t)ls[w]*HH;
    const float* r = XR + (size_t)lr[w]*HH;
    float4 vm = *(const float4*)(m + lane*4);
    float4 vs = *(const float4*)(s + lane*4);
    float4 vr = *(const float4*)(r + lane*4);
    float ds = vs.x*vm.x + vs.y*vm.y + vs.z*vm.z + vs.w*vm.w;
    float dr = vr.x*vm.x + vr.y*vm.y + vr.z*vm.z + vr.w*vm.w;
    #pragma unroll
    for (int d = 16; d; d >>= 1){
        ds += __shfl_xor_sync(0xffffffffu, ds, d);
        dr += __shfl_xor_sync(0xffffffffu, dr, d);
    }
    if (lane == 0){ out[w] = ds; out[LL + w] = dr; }
}

// ---------------- host ----------------
static inline void* symaddr(const void* sym){
    void* p = nullptr;
    cudaGetSymbolAddress(&p, sym);
    return p;
}

extern "C" void kernel_launch(void* const* d_in, const int* in_sizes, int n_in,
                              void* d_out, int out_size){
    const float* emb_s  = (const float*)d_in[0];
    const float* emb_m  = (const float*)d_in[1];
    const float* emb_r  = (const float*)d_in[2];
    const float* sageWl = (const float*)d_in[3];
    const float* sageBl = (const float*)d_in[4];
    const float* sageWr = (const float*)d_in[5];
    const float* gcnW   = (const float*)d_in[6];
    const float* gcnB   = (const float*)d_in[7];
    const int* src_sm   = (const int*)d_in[8];
    const int* dst_sm   = (const int*)d_in[9];
    const int* src_rm   = (const int*)d_in[10];
    const int* dst_rm   = (const int*)d_in[11];
    const int* src_sim  = (const int*)d_in[12];
    const int* dst_sim  = (const int*)d_in[13];
    const int* lbl_s    = (const int*)d_in[14];
    const int* lbl_m    = (const int*)d_in[15];
    const int* lbl_r    = (const int*)d_in[16];
    float* out = (float*)d_out;

    cudaFuncSetAttribute(k_mma3, cudaFuncAttributeMaxDynamicSharedMemorySize, SMEM_MMA_BYTES);

    float* XS = (float*)symaddr(g_XS);
    float* XM = (float*)symaddr(g_XM);
    float* XR = (float*)symaddr(g_XR);
    __nv_bfloat16* Amh = (__nv_bfloat16*)symaddr(g_Amh);
    __nv_bfloat16* Aml = (__nv_bfloat16*)symaddr(g_Aml);
    __nv_bfloat16* Ash = (__nv_bfloat16*)symaddr(g_Ash);
    __nv_bfloat16* Asl = (__nv_bfloat16*)symaddr(g_Asl);
    __nv_bfloat16* Arh = (__nv_bfloat16*)symaddr(g_Arh);
    __nv_bfloat16* Arl = (__nv_bfloat16*)symaddr(g_Arl);
    __nv_bfloat16* Bmh = (__nv_bfloat16*)symaddr(g_Bmh);
    __nv_bfloat16* Bml = (__nv_bfloat16*)symaddr(g_Bml);
    __nv_bfloat16* Bsh = (__nv_bfloat16*)symaddr(g_Bsh);
    __nv_bfloat16* Bsl = (__nv_bfloat16*)symaddr(g_Bsl);
    __nv_bfloat16* Brh = (__nv_bfloat16*)symaddr(g_Brh);
    __nv_bfloat16* Brl = (__nv_bfloat16*)symaddr(g_Brl);
    float* biasM = (float*)symaddr(g_biasM);
    int* adj0 = (int*)symaddr(g_adj0);
    int* adj1 = (int*)symaddr(g_adj1);
    int* adj2 = (int*)symaddr(g_adj2);
    int* adj3 = (int*)symaddr(g_adj3);
    int* adj4 = (int*)symaddr(g_adj4);
    int* adj5 = (int*)symaddr(g_adj5);
    int* off0 = (int*)symaddr(g_off0);
    int* off1 = (int*)symaddr(g_off1);
    int* off2 = (int*)symaddr(g_off2);
    int* off3 = (int*)symaddr(g_off3);
    int* off4 = (int*)symaddr(g_off4);
    int* off5 = (int*)symaddr(g_off5);
    int* cnt6  = (int*)symaddr(g_cnt6);
    int* incl6 = (int*)symaddr(g_incl6);
    int* cur6  = (int*)symaddr(g_cur6);
    int* bsum6 = (int*)symaddr(g_bsums6);
    float* dinvF = (float*)symaddr(g_dinvF);
    float* dinvR = (float*)symaddr(g_dinvR);

    // ---- batched CSR build ----
    CsrArgs ca;
    ca.k0 = dst_sm;  ca.v0 = src_sm;
    ca.k1 = src_sm;  ca.v1 = dst_sm;
    ca.k2 = dst_rm;  ca.v2 = src_rm;
    ca.k3 = src_rm;  ca.v3 = dst_rm;
    ca.k4 = dst_sim; ca.v4 = src_sim;
    ca.k5 = src_sim; ca.v5 = dst_sim;
    OffPtrs op = { off0, off1, off2, off3, off4, off5 };
    AdjPtrs ap = { adj0, adj1, adj2, adj3, adj4, adj5 };

    k_zero_i<<<CDIV(CNT_TOT,256),256>>>(cnt6, CNT_TOT);
    k_count_all<<<EDGE_BLKS,256>>>(ca, cnt6);
    k_scan1_all<<<SCAN_BLKS,1024>>>(cnt6, incl6, bsum6);
    k_scan2_all<<<6,1024>>>(bsum6);
    k_scan3_all<<<SCAN_BLKS,1024>>>(incl6, bsum6, cnt6, op, cur6);
    k_fill_all<<<EDGE_BLKS,256>>>(ca, ap, cur6);
    k_dinv2<<<CDIV(NMm,256),256>>>(off4, off5, dinvF, dinvR);

    const int HW = HH*HH;

    for (int l = 0; l < 2; l++){
        const float* xs = l ? XS : emb_s;
        const float* xm = l ? XM : emb_m;
        const float* xr = l ? XR : emb_r;
        float* XSo = XS + (size_t)l*NSs*HH;
        float* XMo = XM + (size_t)l*NMm*HH;
        float* XRo = XR + (size_t)l*NRr*HH;

        WArgs wa;
        wa.Wl0 = sageWl + (size_t)(l*4+0)*HW;
        wa.Wl1 = sageWl + (size_t)(l*4+1)*HW;
        wa.Wl2 = sageWl + (size_t)(l*4+2)*HW;
        wa.Wl3 = sageWl + (size_t)(l*4+3)*HW;
        wa.bl0 = sageBl + (size_t)(l*4+0)*HH;
        wa.bl2 = sageBl + (size_t)(l*4+2)*HH;
        wa.Wr0 = sageWr + (size_t)(l*4+0)*HW;
        wa.Wr1 = sageWr + (size_t)(l*4+1)*HW;
        wa.Wr2 = sageWr + (size_t)(l*4+2)*HW;
        wa.Wr3 = sageWr + (size_t)(l*4+3)*HW;
        wa.gW0 = gcnW + (size_t)(l*2+0)*HW;
        wa.gW1 = gcnW + (size_t)(l*2+1)*HW;
        wa.gb0 = gcnB + (size_t)(l*2+0)*HH;
        wa.gb1 = gcnB + (size_t)(l*2+1)*HH;
        wa.Bmh = Bmh; wa.Bml = Bml; wa.Bsh = Bsh; wa.Bsl = Bsl;
        wa.Brh = Brh; wa.Brl = Brl; wa.biasM = biasM;

        AggArgs aa;
        aa.xs = xs; aa.xm = xm; aa.xr = xr;
        aa.adj0 = adj0; aa.off0 = off0;
        aa.adj2 = adj2; aa.off2 = off2;
        aa.adj4 = adj4; aa.off4 = off4;
        aa.adj5 = adj5; aa.off5 = off5;
        aa.adj1 = adj1; aa.off1 = off1;
        aa.adj3 = adj3; aa.off3 = off3;
        aa.dinvF = dinvF; aa.dinvR = dinvR;
        aa.Amh = Amh; aa.Aml = Aml; aa.Ash = Ash; aa.Asl = Asl; aa.Arh = Arh; aa.Arl = Arl;

        // one prep launch: all aggregation + weight staging
        k_prep_all<<<AS11,256>>>(aa, wa);

        const float* bl1 = sageBl + (size_t)(l*4+1)*HH;
        const float* bl3 = sageBl + (size_t)(l*4+3)*HH;
        // one batched GEMM launch: m + s + r (bias+relu fused)
        k_mma3<<<MB_TOT,256,SMEM_MMA_BYTES>>>(
            Amh, Aml, Bmh, Bml, biasM, XMo,
            Ash, Asl, Bsh, Bsl, bl1, XSo,
            Arh, Arl, Brh, Brl, bl3, XRo);
    }

    const float* XSf = XS + (size_t)1*NSs*HH;
    const float* XMf = XM + (size_t)1*NMm*HH;
    const float* XRf = XR + (size_t)1*NRr*HH;
    k_pred<<<CDIV(LL,8),256>>>(XSf, XMf, XRf, lbl_s, lbl_m, lbl_r, out);

    (void)in_sizes; (void)n_in; (void)out_size;
}